// round 4
// baseline (speedup 1.0000x reference)
#include <cuda_runtime.h>
#include <math.h>

#define NN 50000
#define MAXE 1700000
#define BN_EPS 1e-5f
#define L2_EPS 1e-12f

// ---------------- scratch (static device globals; no allocation) ----------------
__device__ float g_dinv[NN];                       // rsqrt(degree+1)
__device__ __align__(16) float g_t[NN * 64];       // t = h @ W (pre-aggregation)
__device__ __align__(16) float g_agg[NN * 64];     // aggregation result
__device__ __align__(16) float g_h[NN * 64];       // encoder output
__device__ int   g_degcnt[NN];                     // in-degree (no self loop)
__device__ int   g_start[NN + 1];                  // CSR row starts
__device__ int   g_cursor[NN];                     // placement cursors
__device__ __align__(8) int2 g_csr[MAXE];          // {src, coef bits} sorted by dst
__device__ float g_stats[128];                     // [0:64) sum, [64:128) sumsq
__device__ float g_a[64];                          // BN fold: y = x*a + c
__device__ float g_c[64];
__device__ int   g_not64;                          // 1 if edge_index is int32 layout

// ---------------- edge_index dtype detection ----------------
__global__ void detect_kernel(const int* __restrict__ w, int ne) {
    int i = threadIdx.x;
    int nz = 0;
    for (int k = 2 * i + 1; k < 2048 && k < 2 * ne; k += 512)
        nz |= (w[k] != 0);
    if (nz) atomicExch(&g_not64, 1);
}
__global__ void zero_flag_kernel() { if (threadIdx.x == 0) g_not64 = 0; }

__global__ void zero_deg_kernel() {
    int i = blockIdx.x * blockDim.x + threadIdx.x;
    if (i < NN) g_degcnt[i] = 0;
}

// in-degree histogram (int atomics -> REDG aggregation)
__global__ void deg_kernel(const int* __restrict__ w, int ne) {
    int e = blockIdx.x * blockDim.x + threadIdx.x;
    if (e >= ne) return;
    int d = g_not64 ? w[ne + e] : w[2 * (ne + e)];
    atomicAdd(&g_degcnt[d], 1);
}

// single-block exclusive scan over degcnt; also writes dinv and cursors
__global__ void __launch_bounds__(1024)
scan_kernel() {
    const int T = 1024;
    const int CH = (NN + T - 1) / T;     // 49
    int t = threadIdx.x;
    int lo = t * CH, hi = min(lo + CH, NN);

    int s = 0;
    for (int i = lo; i < hi; i++) s += g_degcnt[i];

    __shared__ int sh[T];
    sh[t] = s;
    __syncthreads();
    // Hillis-Steele inclusive scan
    for (int off = 1; off < T; off <<= 1) {
        int v = (t >= off) ? sh[t - off] : 0;
        __syncthreads();
        sh[t] += v;
        __syncthreads();
    }
    int run = sh[t] - s;                 // exclusive prefix
    for (int i = lo; i < hi; i++) {
        int c = g_degcnt[i];
        g_start[i] = run;
        g_cursor[i] = run;
        g_dinv[i] = rsqrtf((float)c + 1.0f);
        run += c;
    }
    if (t == T - 1) g_start[NN] = run;
}

// place edges into CSR bins (order within bin arbitrary)
__global__ void place_kernel(const int* __restrict__ w, int ne) {
    int e = blockIdx.x * blockDim.x + threadIdx.x;
    if (e >= ne) return;
    int s, d;
    if (g_not64) { s = w[e];     d = w[ne + e]; }
    else         { s = w[2 * e]; d = w[2 * (ne + e)]; }
    float cf = g_dinv[s] * g_dinv[d];
    int pos = atomicAdd(&g_cursor[d], 1);
    g_csr[pos] = make_int2(s, __float_as_int(cf));
}

__global__ void zero_stats_kernel() {
    int i = threadIdx.x;
    if (i < 128) g_stats[i] = 0.0f;
}

// ---------------- GEMM:  out[row, :] = in[row, :K] @ W[K, NOUT]  ----------------
// EPI: 0 = +bias store | 1 = +bias relu store | 2 = raw store (bias handled in gather)
// INAFF: per-column affine on input (BN fold); INRELU: relu after affine
template<int K, int NOUT, int EPI, bool INAFF, bool INRELU>
__global__ void __launch_bounds__(128)
gemm_kernel(const float* __restrict__ in, const float* __restrict__ W,
            const float* __restrict__ bias, float* __restrict__ out, int n)
{
    __shared__ float Ws[K * NOUT];
    __shared__ float bs[NOUT];
    __shared__ float as_[64], cs_[64];

    for (int i = threadIdx.x; i < K * NOUT; i += blockDim.x) Ws[i] = W[i];
    if (EPI != 2 && threadIdx.x < NOUT) bs[threadIdx.x] = bias[threadIdx.x];
    if (INAFF && threadIdx.x < K) {
        as_[threadIdx.x] = g_a[threadIdx.x];
        cs_[threadIdx.x] = g_c[threadIdx.x];
    }
    __syncthreads();

    int row = blockIdx.x * blockDim.x + threadIdx.x;
    if (row >= n) return;

    const float4* xr4 = (const float4*)(in + (long long)row * K);

    float acc[NOUT];
#pragma unroll
    for (int j = 0; j < NOUT; j++) acc[j] = (EPI == 2) ? 0.0f : bs[j];

#pragma unroll
    for (int kk = 0; kk < K; kk += 16) {
        float4 xv0 = xr4[kk / 4 + 0];
        float4 xv1 = xr4[kk / 4 + 1];
        float4 xv2 = xr4[kk / 4 + 2];
        float4 xv3 = xr4[kk / 4 + 3];
        float xs[16] = {xv0.x, xv0.y, xv0.z, xv0.w,
                        xv1.x, xv1.y, xv1.z, xv1.w,
                        xv2.x, xv2.y, xv2.z, xv2.w,
                        xv3.x, xv3.y, xv3.z, xv3.w};
        if (INAFF) {
#pragma unroll
            for (int i = 0; i < 16; i++) {
                xs[i] = fmaf(xs[i], as_[kk + i], cs_[kk + i]);
                if (INRELU) xs[i] = fmaxf(xs[i], 0.0f);
            }
        }
#pragma unroll
        for (int i = 0; i < 16; i++) {
            float xk = xs[i];
            const float* wr = Ws + (kk + i) * NOUT;
#pragma unroll
            for (int j = 0; j < NOUT; j += 4) {
                float4 w = *(const float4*)(wr + j);
                acc[j + 0] = fmaf(xk, w.x, acc[j + 0]);
                acc[j + 1] = fmaf(xk, w.y, acc[j + 1]);
                acc[j + 2] = fmaf(xk, w.z, acc[j + 2]);
                acc[j + 3] = fmaf(xk, w.w, acc[j + 3]);
            }
        }
    }

    float4* o4 = (float4*)(out + (long long)row * NOUT);
#pragma unroll
    for (int j = 0; j < NOUT; j += 4) {
        float4 v = make_float4(acc[j], acc[j + 1], acc[j + 2], acc[j + 3]);
        if (EPI == 1) {
            v.x = fmaxf(v.x, 0.0f); v.y = fmaxf(v.y, 0.0f);
            v.z = fmaxf(v.z, 0.0f); v.w = fmaxf(v.w, 0.0f);
        }
        o4[j / 4] = v;
    }
}

// ---------------- CSR gather: agg[n] = sum_e coef*t[src] + t[n]*dinv^2 + bias ----------------
// C=64: warp per node, lane holds cols (2*lane, 2*lane+1) via float2.
__global__ void __launch_bounds__(256)
gather64_kernel(const float* __restrict__ bias)
{
    int n = blockIdx.x * 8 + (threadIdx.x >> 5);
    if (n >= NN) return;
    int lane = threadIdx.x & 31;

    int e = g_start[n], e1 = g_start[n + 1];
    const float2* T2 = (const float2*)g_t;

    float a0 = 0.0f, a1 = 0.0f;
    for (; e + 4 <= e1; e += 4) {
        int2 p0 = g_csr[e], p1 = g_csr[e + 1], p2 = g_csr[e + 2], p3 = g_csr[e + 3];
        float2 v0 = T2[p0.x * 32 + lane];
        float2 v1 = T2[p1.x * 32 + lane];
        float2 v2 = T2[p2.x * 32 + lane];
        float2 v3 = T2[p3.x * 32 + lane];
        float c0 = __int_as_float(p0.y), c1 = __int_as_float(p1.y);
        float c2 = __int_as_float(p2.y), c3 = __int_as_float(p3.y);
        a0 = fmaf(c0, v0.x, a0); a1 = fmaf(c0, v0.y, a1);
        a0 = fmaf(c1, v1.x, a0); a1 = fmaf(c1, v1.y, a1);
        a0 = fmaf(c2, v2.x, a0); a1 = fmaf(c2, v2.y, a1);
        a0 = fmaf(c3, v3.x, a0); a1 = fmaf(c3, v3.y, a1);
    }
    for (; e < e1; e++) {
        int2 p = g_csr[e];
        float2 v = T2[p.x * 32 + lane];
        float c = __int_as_float(p.y);
        a0 = fmaf(c, v.x, a0); a1 = fmaf(c, v.y, a1);
    }

    float dv = g_dinv[n], d2 = dv * dv;
    float2 sv = T2[n * 32 + lane];
    a0 = fmaf(sv.x, d2, a0) + bias[2 * lane];
    a1 = fmaf(sv.y, d2, a1) + bias[2 * lane + 1];
    ((float2*)g_agg)[n * 32 + lane] = make_float2(a0, a1);
}

// C=32: warp per node, lane = col.
__global__ void __launch_bounds__(256)
gather32_kernel(const float* __restrict__ bias)
{
    int n = blockIdx.x * 8 + (threadIdx.x >> 5);
    if (n >= NN) return;
    int lane = threadIdx.x & 31;

    int e = g_start[n], e1 = g_start[n + 1];
    const float* T = g_t;

    float a0 = 0.0f;
    for (; e + 4 <= e1; e += 4) {
        int2 p0 = g_csr[e], p1 = g_csr[e + 1], p2 = g_csr[e + 2], p3 = g_csr[e + 3];
        float v0 = T[p0.x * 32 + lane];
        float v1 = T[p1.x * 32 + lane];
        float v2 = T[p2.x * 32 + lane];
        float v3 = T[p3.x * 32 + lane];
        a0 = fmaf(__int_as_float(p0.y), v0, a0);
        a0 = fmaf(__int_as_float(p1.y), v1, a0);
        a0 = fmaf(__int_as_float(p2.y), v2, a0);
        a0 = fmaf(__int_as_float(p3.y), v3, a0);
    }
    for (; e < e1; e++) {
        int2 p = g_csr[e];
        a0 = fmaf(__int_as_float(p.y), T[p.x * 32 + lane], a0);
    }

    float dv = g_dinv[n], d2 = dv * dv;
    a0 = fmaf(T[n * 32 + lane], d2, a0) + bias[lane];
    g_agg[n * 32 + lane] = a0;
}

// ---------------- BN statistics (column sum / sumsq) ----------------
template<int C>
__global__ void __launch_bounds__(256)
bnstats_kernel(const float* __restrict__ x, int n)
{
    const int BLK = 256;
    const int GR = BLK / C;
    int col = threadIdx.x & (C - 1);
    int grp = threadIdx.x / C;

    float s = 0.0f, s2 = 0.0f;
    for (int r = blockIdx.x * GR + grp; r < n; r += gridDim.x * GR) {
        float v = x[(long long)r * C + col];
        s += v;
        s2 = fmaf(v, v, s2);
    }
    __shared__ float sh0[BLK], sh1[BLK];
    sh0[threadIdx.x] = s;
    sh1[threadIdx.x] = s2;
    __syncthreads();
    if (grp == 0) {
#pragma unroll
        for (int g = 1; g < GR; g++) {
            s  += sh0[g * C + col];
            s2 += sh1[g * C + col];
        }
        atomicAdd(&g_stats[col], s);
        atomicAdd(&g_stats[64 + col], s2);
    }
}

template<int C>
__global__ void bnparams_kernel(const float* __restrict__ gamma,
                                const float* __restrict__ beta, float inv_n)
{
    int t = threadIdx.x;
    if (t < C) {
        float s = g_stats[t], s2 = g_stats[64 + t];
        float mu = s * inv_n;
        float var = fmaxf(s2 * inv_n - mu * mu, 0.0f);
        float rstd = rsqrtf(var + BN_EPS);
        float a = rstd * gamma[t];
        g_a[t] = a;
        g_c[t] = fmaf(-mu, a, beta[t]);
    }
}

// Final: BN (32 cols) + row L2 normalize. Warp per row (lane == column).
__global__ void __launch_bounds__(256)
final_kernel(float* __restrict__ out, int n)
{
    int t = blockIdx.x * blockDim.x + threadIdx.x;
    int row = t >> 5, lane = t & 31;
    if (row >= n) return;
    float v = fmaf(g_agg[(long long)row * 32 + lane], g_a[lane], g_c[lane]);
    float ss = v * v;
#pragma unroll
    for (int o = 16; o; o >>= 1) ss += __shfl_xor_sync(0xFFFFFFFFu, ss, o);
    out[(long long)row * 32 + lane] = v / fmaxf(sqrtf(ss), L2_EPS);
}

// ---------------- launch ----------------
extern "C" void kernel_launch(void* const* d_in, const int* in_sizes, int n_in,
                              void* d_out, int out_size)
{
    const float* x  = (const float*)d_in[0];
    const int*   ew = (const int*)d_in[1];
    const float* ne_w1 = (const float*)d_in[2];
    const float* ne_b1 = (const float*)d_in[3];
    const float* ne_g  = (const float*)d_in[4];
    const float* ne_be = (const float*)d_in[5];
    const float* ne_w2 = (const float*)d_in[6];
    const float* ne_b2 = (const float*)d_in[7];
    const float* c1_w = (const float*)d_in[8];
    const float* c1_b = (const float*)d_in[9];
    const float* g1   = (const float*)d_in[10];
    const float* be1  = (const float*)d_in[11];
    const float* c2_w = (const float*)d_in[12];
    const float* c2_b = (const float*)d_in[13];
    const float* g2   = (const float*)d_in[14];
    const float* be2  = (const float*)d_in[15];
    const float* c3_w = (const float*)d_in[16];
    const float* c3_b = (const float*)d_in[17];
    const float* g3   = (const float*)d_in[18];
    const float* be3  = (const float*)d_in[19];
    float* out = (float*)d_out;

    int ne = in_sizes[1] / 2;
    if (ne > MAXE) ne = MAXE;

    const float inv_n = 1.0f / (float)NN;
    const int NB = (NN + 255) / 256;
    const int EB = (ne + 255) / 256;
    const int GB = (NN + 127) / 128;
    const int WB = (NN + 7) / 8;        // warp-per-node blocks (256 thr)

    float* dT;   cudaGetSymbolAddress((void**)&dT,   g_t);
    float* dAgg; cudaGetSymbolAddress((void**)&dAgg, g_agg);
    float* dH;   cudaGetSymbolAddress((void**)&dH,   g_h);

    // ---- CSR build
    zero_flag_kernel<<<1, 32>>>();
    detect_kernel<<<1, 256>>>(ew, ne);
    zero_deg_kernel<<<NB, 256>>>();
    deg_kernel<<<EB, 256>>>(ew, ne);
    scan_kernel<<<1, 1024>>>();
    place_kernel<<<EB, 256>>>(ew, ne);

    // ---- node encoder: relu(x@W1+b1) -> BN (folded) -> @W2+b2
    gemm_kernel<32, 64, 1, false, false><<<GB, 128>>>(x, ne_w1, ne_b1, dT, NN);
    zero_stats_kernel<<<1, 128>>>();
    bnstats_kernel<64><<<256, 256>>>(dT, NN);
    bnparams_kernel<64><<<1, 64>>>(ne_g, ne_be, inv_n);
    gemm_kernel<64, 64, 0, true, false><<<GB, 128>>>(dT, ne_w2, ne_b2, dH, NN);

    // ---- conv layer 1
    gemm_kernel<64, 64, 2, false, false><<<GB, 128>>>(dH, c1_w, c1_b, dT, NN);
    gather64_kernel<<<WB, 256>>>(c1_b);
    zero_stats_kernel<<<1, 128>>>();
    bnstats_kernel<64><<<256, 256>>>(dAgg, NN);
    bnparams_kernel<64><<<1, 64>>>(g1, be1, inv_n);

    // ---- conv layer 2 (BN+relu folded into GEMM input)
    gemm_kernel<64, 64, 2, true, true><<<GB, 128>>>(dAgg, c2_w, c2_b, dT, NN);
    gather64_kernel<<<WB, 256>>>(c2_b);
    zero_stats_kernel<<<1, 128>>>();
    bnstats_kernel<64><<<256, 256>>>(dAgg, NN);
    bnparams_kernel<64><<<1, 64>>>(g2, be2, inv_n);

    // ---- conv layer 3 (out=32)
    gemm_kernel<64, 32, 2, true, true><<<GB, 128>>>(dAgg, c3_w, c3_b, dT, NN);
    gather32_kernel<<<WB, 256>>>(c3_b);
    zero_stats_kernel<<<1, 128>>>();
    bnstats_kernel<32><<<256, 256>>>(dAgg, NN);
    bnparams_kernel<32><<<1, 32>>>(g3, be3, inv_n);
    final_kernel<<<(NN * 32 + 255) / 256, 256>>>(out, NN);
}

// round 5
// speedup vs baseline: 1.1429x; 1.1429x over previous
#include <cuda_runtime.h>
#include <math.h>

#define NN 50000
#define MAXE 1700000
#define BN_EPS 1e-5f
#define L2_EPS 1e-12f
#define INVN (1.0f / 50000.0f)

// ---------------- scratch (static device globals; no allocation) ----------------
__device__ float g_dinv[NN];                       // rsqrt(degree+1)
__device__ __align__(16) float g_t[NN * 64];       // t = h @ W (pre-aggregation)
__device__ __align__(16) float g_agg[NN * 64];     // aggregation result
__device__ __align__(16) float g_h[NN * 64];       // encoder output
__device__ int   g_degcnt[NN];                     // in-degree (no self loop)
__device__ int   g_start[NN + 1];                  // CSR row starts
__device__ int   g_cursor[NN];                     // placement cursors
__device__ __align__(8) int2 g_csr[MAXE];          // {src, coef bits} grouped by dst
__device__ float g_stats4[4 * 128];                // 4 BN stat slots: [sum(64) | sumsq(64)]
__device__ int   g_not64;                          // 1 if edge_index is int32 layout

// ---------------- init: zero flag, degcnt, all stat slots ----------------
__global__ void init_kernel() {
    int i = blockIdx.x * blockDim.x + threadIdx.x;
    if (i < NN) g_degcnt[i] = 0;
    if (i < 512) g_stats4[i] = 0.0f;
    if (i == 0) g_not64 = 0;
}

// ---------------- edge_index dtype detection ----------------
__global__ void detect_kernel(const int* __restrict__ w, int ne) {
    int i = threadIdx.x;
    int nz = 0;
    for (int k = 2 * i + 1; k < 2048 && k < 2 * ne; k += 512)
        nz |= (w[k] != 0);
    if (nz) atomicExch(&g_not64, 1);
}

// in-degree histogram
__global__ void deg_kernel(const int* __restrict__ w, int ne) {
    int e = blockIdx.x * blockDim.x + threadIdx.x;
    if (e >= ne) return;
    int d = g_not64 ? w[ne + e] : w[2 * (ne + e)];
    atomicAdd(&g_degcnt[d], 1);
}

// single-block exclusive scan; also writes dinv and cursors
__global__ void __launch_bounds__(1024)
scan_kernel() {
    const int T = 1024;
    const int CH = (NN + T - 1) / T;
    int t = threadIdx.x;
    int lo = t * CH, hi = min(lo + CH, NN);

    int s = 0;
    for (int i = lo; i < hi; i++) s += g_degcnt[i];

    __shared__ int sh[T];
    sh[t] = s;
    __syncthreads();
    for (int off = 1; off < T; off <<= 1) {
        int v = (t >= off) ? sh[t - off] : 0;
        __syncthreads();
        sh[t] += v;
        __syncthreads();
    }
    int run = sh[t] - s;
    for (int i = lo; i < hi; i++) {
        int c = g_degcnt[i];
        g_start[i] = run;
        g_cursor[i] = run;
        g_dinv[i] = rsqrtf((float)c + 1.0f);
        run += c;
    }
    if (t == T - 1) g_start[NN] = run;
}

// place edges into CSR bins
__global__ void place_kernel(const int* __restrict__ w, int ne) {
    int e = blockIdx.x * blockDim.x + threadIdx.x;
    if (e >= ne) return;
    int s, d;
    if (g_not64) { s = w[e];     d = w[ne + e]; }
    else         { s = w[2 * e]; d = w[2 * (ne + e)]; }
    float cf = g_dinv[s] * g_dinv[d];
    int pos = atomicAdd(&g_cursor[d], 1);
    g_csr[pos] = make_int2(s, __float_as_int(cf));
}

// ---------------- GEMM (2 threads per row; half = tid>>6 owns NOUT/2 cols) ----------------
// EPI: 0 = +bias store | 1 = +bias relu store | 2 = raw store (bias in gather)
// INAFF: BN fold on input, params computed in-prologue from stats/gamma/beta
// INRELU: relu after the affine
template<int K, int NOUT, int EPI, bool INAFF, bool INRELU>
__global__ void __launch_bounds__(128)
gemm_kernel(const float* __restrict__ in, const float* __restrict__ W,
            const float* __restrict__ bias, float* __restrict__ out, int n,
            const float* __restrict__ stats, const float* __restrict__ gamma,
            const float* __restrict__ beta)
{
    const int NH = NOUT / 2;
    __shared__ float Ws[K * NOUT];
    __shared__ float bs[NOUT];
    __shared__ float as_[64], cs_[64];

    for (int i = threadIdx.x; i < K * NOUT; i += 128) Ws[i] = W[i];
    if (EPI != 2 && threadIdx.x < NOUT) bs[threadIdx.x] = bias[threadIdx.x];
    if (INAFF && threadIdx.x < K) {
        int t = threadIdx.x;
        float s = stats[t], s2 = stats[64 + t];
        float mu = s * INVN;
        float var = fmaxf(s2 * INVN - mu * mu, 0.0f);
        float a = rsqrtf(var + BN_EPS) * gamma[t];
        as_[t] = a;
        cs_[t] = fmaf(-mu, a, beta[t]);
    }
    __syncthreads();

    int row  = blockIdx.x * 64 + (threadIdx.x & 63);
    int half = threadIdx.x >> 6;
    if (row >= n) return;

    const float4* xr4 = (const float4*)(in + (long long)row * K);

    float acc[NH];
#pragma unroll
    for (int j = 0; j < NH; j++) acc[j] = (EPI == 2) ? 0.0f : bs[half * NH + j];

#pragma unroll
    for (int kk = 0; kk < K; kk += 16) {
        float4 xv0 = xr4[kk / 4 + 0];
        float4 xv1 = xr4[kk / 4 + 1];
        float4 xv2 = xr4[kk / 4 + 2];
        float4 xv3 = xr4[kk / 4 + 3];
        float xs[16] = {xv0.x, xv0.y, xv0.z, xv0.w,
                        xv1.x, xv1.y, xv1.z, xv1.w,
                        xv2.x, xv2.y, xv2.z, xv2.w,
                        xv3.x, xv3.y, xv3.z, xv3.w};
        if (INAFF) {
#pragma unroll
            for (int i = 0; i < 16; i++) {
                xs[i] = fmaf(xs[i], as_[kk + i], cs_[kk + i]);
                if (INRELU) xs[i] = fmaxf(xs[i], 0.0f);
            }
        }
#pragma unroll
        for (int i = 0; i < 16; i++) {
            float xk = xs[i];
            const float* wr = Ws + (kk + i) * NOUT + half * NH;
#pragma unroll
            for (int j = 0; j < NH; j += 4) {
                float4 w = *(const float4*)(wr + j);
                acc[j + 0] = fmaf(xk, w.x, acc[j + 0]);
                acc[j + 1] = fmaf(xk, w.y, acc[j + 1]);
                acc[j + 2] = fmaf(xk, w.z, acc[j + 2]);
                acc[j + 3] = fmaf(xk, w.w, acc[j + 3]);
            }
        }
    }

    float4* o4 = (float4*)(out + (long long)row * NOUT + half * NH);
#pragma unroll
    for (int j = 0; j < NH; j += 4) {
        float4 v = make_float4(acc[j], acc[j + 1], acc[j + 2], acc[j + 3]);
        if (EPI == 1) {
            v.x = fmaxf(v.x, 0.0f); v.y = fmaxf(v.y, 0.0f);
            v.z = fmaxf(v.z, 0.0f); v.w = fmaxf(v.w, 0.0f);
        }
        o4[j / 4] = v;
    }
}

// ---------------- CSR gather: agg[n] = sum_e coef*t[src] + t[n]*dinv^2 + bias ----------------
__global__ void __launch_bounds__(256)
gather64_kernel(const float* __restrict__ bias)
{
    int n = blockIdx.x * 8 + (threadIdx.x >> 5);
    if (n >= NN) return;
    int lane = threadIdx.x & 31;

    int e = g_start[n], e1 = g_start[n + 1];
    const float2* T2 = (const float2*)g_t;

    float a0 = 0.0f, a1 = 0.0f;
    for (; e + 8 <= e1; e += 8) {
        int2 p[8];
#pragma unroll
        for (int q = 0; q < 8; q++) p[q] = g_csr[e + q];
        float2 v[8];
#pragma unroll
        for (int q = 0; q < 8; q++) v[q] = T2[p[q].x * 32 + lane];
#pragma unroll
        for (int q = 0; q < 8; q++) {
            float c = __int_as_float(p[q].y);
            a0 = fmaf(c, v[q].x, a0);
            a1 = fmaf(c, v[q].y, a1);
        }
    }
    for (; e < e1; e++) {
        int2 p = g_csr[e];
        float2 v = T2[p.x * 32 + lane];
        float c = __int_as_float(p.y);
        a0 = fmaf(c, v.x, a0); a1 = fmaf(c, v.y, a1);
    }

    float dv = g_dinv[n], d2 = dv * dv;
    float2 sv = T2[n * 32 + lane];
    a0 = fmaf(sv.x, d2, a0) + bias[2 * lane];
    a1 = fmaf(sv.y, d2, a1) + bias[2 * lane + 1];
    ((float2*)g_agg)[n * 32 + lane] = make_float2(a0, a1);
}

__global__ void __launch_bounds__(256)
gather32_kernel(const float* __restrict__ bias)
{
    int n = blockIdx.x * 8 + (threadIdx.x >> 5);
    if (n >= NN) return;
    int lane = threadIdx.x & 31;

    int e = g_start[n], e1 = g_start[n + 1];
    const float* T = g_t;

    float a0 = 0.0f;
    for (; e + 8 <= e1; e += 8) {
        int2 p[8];
#pragma unroll
        for (int q = 0; q < 8; q++) p[q] = g_csr[e + q];
        float v[8];
#pragma unroll
        for (int q = 0; q < 8; q++) v[q] = T[p[q].x * 32 + lane];
#pragma unroll
        for (int q = 0; q < 8; q++)
            a0 = fmaf(__int_as_float(p[q].y), v[q], a0);
    }
    for (; e < e1; e++) {
        int2 p = g_csr[e];
        a0 = fmaf(__int_as_float(p.y), T[p.x * 32 + lane], a0);
    }

    float dv = g_dinv[n], d2 = dv * dv;
    a0 = fmaf(T[n * 32 + lane], d2, a0) + bias[lane];
    g_agg[n * 32 + lane] = a0;
}

// ---------------- BN statistics (column sum / sumsq) ----------------
template<int C>
__global__ void __launch_bounds__(256)
bnstats_kernel(const float* __restrict__ x, int n, float* __restrict__ stats)
{
    const int BLK = 256;
    const int GR = BLK / C;
    int col = threadIdx.x & (C - 1);
    int grp = threadIdx.x / C;

    float s = 0.0f, s2 = 0.0f;
    for (int r = blockIdx.x * GR + grp; r < n; r += gridDim.x * GR) {
        float v = x[(long long)r * C + col];
        s += v;
        s2 = fmaf(v, v, s2);
    }
    __shared__ float sh0[BLK], sh1[BLK];
    sh0[threadIdx.x] = s;
    sh1[threadIdx.x] = s2;
    __syncthreads();
    if (grp == 0) {
#pragma unroll
        for (int g = 1; g < GR; g++) {
            s  += sh0[g * C + col];
            s2 += sh1[g * C + col];
        }
        atomicAdd(&stats[col], s);
        atomicAdd(&stats[64 + col], s2);
    }
}

// Final: BN params inline + row L2 normalize. Warp per row (lane == column).
__global__ void __launch_bounds__(256)
final_kernel(const float* __restrict__ stats, const float* __restrict__ gamma,
             const float* __restrict__ beta, float* __restrict__ out, int n)
{
    int t = blockIdx.x * blockDim.x + threadIdx.x;
    int row = t >> 5, lane = t & 31;
    if (row >= n) return;
    float s = stats[lane], s2 = stats[64 + lane];
    float mu = s * INVN;
    float var = fmaxf(s2 * INVN - mu * mu, 0.0f);
    float a = rsqrtf(var + BN_EPS) * gamma[lane];
    float c = fmaf(-mu, a, beta[lane]);
    float v = fmaf(g_agg[(long long)row * 32 + lane], a, c);
    float ss = v * v;
#pragma unroll
    for (int o = 16; o; o >>= 1) ss += __shfl_xor_sync(0xFFFFFFFFu, ss, o);
    out[(long long)row * 32 + lane] = v / fmaxf(sqrtf(ss), L2_EPS);
}

// ---------------- launch ----------------
extern "C" void kernel_launch(void* const* d_in, const int* in_sizes, int n_in,
                              void* d_out, int out_size)
{
    const float* x  = (const float*)d_in[0];
    const int*   ew = (const int*)d_in[1];
    const float* ne_w1 = (const float*)d_in[2];
    const float* ne_b1 = (const float*)d_in[3];
    const float* ne_g  = (const float*)d_in[4];
    const float* ne_be = (const float*)d_in[5];
    const float* ne_w2 = (const float*)d_in[6];
    const float* ne_b2 = (const float*)d_in[7];
    const float* c1_w = (const float*)d_in[8];
    const float* c1_b = (const float*)d_in[9];
    const float* g1   = (const float*)d_in[10];
    const float* be1  = (const float*)d_in[11];
    const float* c2_w = (const float*)d_in[12];
    const float* c2_b = (const float*)d_in[13];
    const float* g2   = (const float*)d_in[14];
    const float* be2  = (const float*)d_in[15];
    const float* c3_w = (const float*)d_in[16];
    const float* c3_b = (const float*)d_in[17];
    const float* g3   = (const float*)d_in[18];
    const float* be3  = (const float*)d_in[19];
    float* out = (float*)d_out;

    int ne = in_sizes[1] / 2;
    if (ne > MAXE) ne = MAXE;

    const int NB = (NN + 255) / 256;
    const int EB = (ne + 255) / 256;
    const int GB = (NN + 63) / 64;      // gemm blocks (128 thr, 64 rows each)
    const int WB = (NN + 7) / 8;        // warp-per-node blocks

    float* dT;   cudaGetSymbolAddress((void**)&dT,   g_t);
    float* dAgg; cudaGetSymbolAddress((void**)&dAgg, g_agg);
    float* dH;   cudaGetSymbolAddress((void**)&dH,   g_h);
    float* dS;   cudaGetSymbolAddress((void**)&dS,   g_stats4);
    float* sA = dS, *sB = dS + 128, *sC = dS + 256, *sD = dS + 384;

    // side stream + events (created once, outside any capture)
    static cudaStream_t s1 = nullptr;
    static cudaEvent_t ev0 = nullptr, ev1 = nullptr;
    if (!s1) {
        cudaStreamCreateWithFlags(&s1, cudaStreamNonBlocking);
        cudaEventCreateWithFlags(&ev0, cudaEventDisableTiming);
        cudaEventCreateWithFlags(&ev1, cudaEventDisableTiming);
    }

    // ---- init + dtype detect (main stream)
    init_kernel<<<NB, 256>>>();
    detect_kernel<<<1, 256>>>(ew, ne);
    cudaEventRecord(ev0, 0);

    // ---- CSR build on side stream (overlaps encoder)
    cudaStreamWaitEvent(s1, ev0, 0);
    deg_kernel<<<EB, 256, 0, s1>>>(ew, ne);
    scan_kernel<<<1, 1024, 0, s1>>>();
    place_kernel<<<EB, 256, 0, s1>>>(ew, ne);
    cudaEventRecord(ev1, s1);

    // ---- node encoder on main stream: relu(x@W1+b1) -> BN(folded) -> @W2+b2
    gemm_kernel<32, 64, 1, false, false><<<GB, 128>>>(x, ne_w1, ne_b1, dT, NN, nullptr, nullptr, nullptr);
    bnstats_kernel<64><<<256, 256>>>(dT, NN, sA);
    gemm_kernel<64, 64, 0, true, false><<<GB, 128>>>(dT, ne_w2, ne_b2, dH, NN, sA, ne_g, ne_be);

    // join: conv layers need the CSR
    cudaStreamWaitEvent(0, ev1, 0);

    // ---- conv layer 1
    gemm_kernel<64, 64, 2, false, false><<<GB, 128>>>(dH, c1_w, c1_b, dT, NN, nullptr, nullptr, nullptr);
    gather64_kernel<<<WB, 256>>>(c1_b);
    bnstats_kernel<64><<<256, 256>>>(dAgg, NN, sB);

    // ---- conv layer 2 (BN+relu folded into GEMM input)
    gemm_kernel<64, 64, 2, true, true><<<GB, 128>>>(dAgg, c2_w, c2_b, dT, NN, sB, g1, be1);
    gather64_kernel<<<WB, 256>>>(c2_b);
    bnstats_kernel<64><<<256, 256>>>(dAgg, NN, sC);

    // ---- conv layer 3 (out=32)
    gemm_kernel<64, 32, 2, true, true><<<GB, 128>>>(dAgg, c3_w, c3_b, dT, NN, sC, g2, be2);
    gather32_kernel<<<WB, 256>>>(c3_b);
    bnstats_kernel<32><<<256, 256>>>(dAgg, NN, sD);

    // ---- final BN + L2 normalize
    final_kernel<<<(NN * 32 + 255) / 256, 256>>>(sD, g3, be3, out, NN);
}

// round 6
// speedup vs baseline: 1.3481x; 1.1795x over previous
#include <cuda_runtime.h>
#include <math.h>

#define NN 50000
#define MAXE 1700000
#define BN_EPS 1e-5f
#define L2_EPS 1e-12f
#define INVN (1.0f / 50000.0f)

#define SCHUNK 256
#define SBLKS ((NN + SCHUNK - 1) / SCHUNK)   // 196

// ---------------- scratch (static device globals; no allocation) ----------------
__device__ float g_dinv[NN];                       // rsqrt(degree+1)
__device__ __align__(16) float g_t[NN * 64];       // t = h @ W (pre-aggregation)
__device__ __align__(16) float g_agg[NN * 64];     // aggregation result
__device__ __align__(16) float g_h[NN * 64];       // encoder output
__device__ int   g_degcnt[NN];                     // in-degree (no self loop)
__device__ int   g_start[NN + 1];                  // CSR row starts
__device__ int   g_cursor[NN];                     // placement cursors
__device__ int   g_bsum[SBLKS];                    // per-block degree sums
__device__ int   g_boff[SBLKS];                    // exclusive block offsets
__device__ __align__(8) int2 g_csr[MAXE];          // {src, coef bits} grouped by dst
__device__ float g_stats4[4 * 128];                // 4 BN stat slots
__device__ int   g_not64;                          // 1 if edge_index is int32 layout

// ---------------- init: zero flag, degcnt, all stat slots ----------------
__global__ void init_kernel() {
    int i = blockIdx.x * blockDim.x + threadIdx.x;
    if (i < NN) g_degcnt[i] = 0;
    if (i < 512) g_stats4[i] = 0.0f;
    if (i == 0) g_not64 = 0;
}

// ---------------- edge_index dtype detection ----------------
__global__ void detect_kernel(const int* __restrict__ w, int ne) {
    int i = threadIdx.x;
    int nz = 0;
    for (int k = 2 * i + 1; k < 2048 && k < 2 * ne; k += 512)
        nz |= (w[k] != 0);
    if (nz) atomicExch(&g_not64, 1);
}

// in-degree histogram
__global__ void deg_kernel(const int* __restrict__ w, int ne) {
    int e = blockIdx.x * blockDim.x + threadIdx.x;
    if (e >= ne) return;
    int d = g_not64 ? w[ne + e] : w[2 * (ne + e)];
    atomicAdd(&g_degcnt[d], 1);
}

// ---------------- decomposed scan ----------------
// 1) per-block sums of degcnt chunks
__global__ void __launch_bounds__(SCHUNK)
bsum_kernel() {
    int i = blockIdx.x * SCHUNK + threadIdx.x;
    int v = (i < NN) ? g_degcnt[i] : 0;
#pragma unroll
    for (int o = 16; o; o >>= 1) v += __shfl_xor_sync(0xFFFFFFFFu, v, o);
    __shared__ int ws[8];
    if ((threadIdx.x & 31) == 0) ws[threadIdx.x >> 5] = v;
    __syncthreads();
    if (threadIdx.x == 0) {
        int s = 0;
#pragma unroll
        for (int k = 0; k < 8; k++) s += ws[k];
        g_bsum[blockIdx.x] = s;
    }
}

// 2) single-block exclusive scan over the SBLKS block sums
__global__ void __launch_bounds__(256)
bscan_kernel() {
    int t = threadIdx.x;
    int v = (t < SBLKS) ? g_bsum[t] : 0;
    int lane = t & 31, warp = t >> 5;
    int x = v;
#pragma unroll
    for (int o = 1; o < 32; o <<= 1) {
        int y = __shfl_up_sync(0xFFFFFFFFu, x, o);
        if (lane >= o) x += y;
    }
    __shared__ int wsum[8];
    if (lane == 31) wsum[warp] = x;
    __syncthreads();
    if (warp == 0) {
        int w = (lane < 8) ? wsum[lane] : 0;
#pragma unroll
        for (int o = 1; o < 8; o <<= 1) {
            int y = __shfl_up_sync(0xFFFFFFFFu, w, o);
            if (lane >= o) w += y;
        }
        if (lane < 8) wsum[lane] = w;
    }
    __syncthreads();
    int incl = x + (warp ? wsum[warp - 1] : 0);
    if (t < SBLKS) g_boff[t] = incl - v;       // exclusive
    if (t == SBLKS - 1) g_start[NN] = incl;    // total edge count
}

// 3) block-local exclusive scan + offset; emit start/cursor/dinv
__global__ void __launch_bounds__(SCHUNK)
expand_kernel() {
    int i = blockIdx.x * SCHUNK + threadIdx.x;
    int v = (i < NN) ? g_degcnt[i] : 0;
    int lane = threadIdx.x & 31, warp = threadIdx.x >> 5;
    int x = v;
#pragma unroll
    for (int o = 1; o < 32; o <<= 1) {
        int y = __shfl_up_sync(0xFFFFFFFFu, x, o);
        if (lane >= o) x += y;
    }
    __shared__ int wsum[8];
    if (lane == 31) wsum[warp] = x;
    __syncthreads();
    if (warp == 0) {
        int w = (lane < 8) ? wsum[lane] : 0;
#pragma unroll
        for (int o = 1; o < 8; o <<= 1) {
            int y = __shfl_up_sync(0xFFFFFFFFu, w, o);
            if (lane >= o) w += y;
        }
        if (lane < 8) wsum[lane] = w;
    }
    __syncthreads();
    int excl = x - v + (warp ? wsum[warp - 1] : 0) + g_boff[blockIdx.x];
    if (i < NN) {
        g_start[i] = excl;
        g_cursor[i] = excl;
        g_dinv[i] = rsqrtf((float)v + 1.0f);
    }
}

// place edges into CSR bins
__global__ void place_kernel(const int* __restrict__ w, int ne) {
    int e = blockIdx.x * blockDim.x + threadIdx.x;
    if (e >= ne) return;
    int s, d;
    if (g_not64) { s = w[e];     d = w[ne + e]; }
    else         { s = w[2 * e]; d = w[2 * (ne + e)]; }
    float cf = g_dinv[s] * g_dinv[d];
    int pos = atomicAdd(&g_cursor[d], 1);
    g_csr[pos] = make_int2(s, __float_as_int(cf));
}

// ---------------- GEMM (2 threads per row; half = tid>>6 owns NOUT/2 cols) ----------------
template<int K, int NOUT, int EPI, bool INAFF, bool INRELU>
__global__ void __launch_bounds__(128)
gemm_kernel(const float* __restrict__ in, const float* __restrict__ W,
            const float* __restrict__ bias, float* __restrict__ out, int n,
            const float* __restrict__ stats, const float* __restrict__ gamma,
            const float* __restrict__ beta)
{
    const int NH = NOUT / 2;
    __shared__ float Ws[K * NOUT];
    __shared__ float bs[NOUT];
    __shared__ float as_[64], cs_[64];

    for (int i = threadIdx.x; i < K * NOUT; i += 128) Ws[i] = W[i];
    if (EPI != 2 && threadIdx.x < NOUT) bs[threadIdx.x] = bias[threadIdx.x];
    if (INAFF && threadIdx.x < K) {
        int t = threadIdx.x;
        float s = stats[t], s2 = stats[64 + t];
        float mu = s * INVN;
        float var = fmaxf(s2 * INVN - mu * mu, 0.0f);
        float a = rsqrtf(var + BN_EPS) * gamma[t];
        as_[t] = a;
        cs_[t] = fmaf(-mu, a, beta[t]);
    }
    __syncthreads();

    int row  = blockIdx.x * 64 + (threadIdx.x & 63);
    int half = threadIdx.x >> 6;
    if (row >= n) return;

    const float4* xr4 = (const float4*)(in + (long long)row * K);

    float acc[NH];
#pragma unroll
    for (int j = 0; j < NH; j++) acc[j] = (EPI == 2) ? 0.0f : bs[half * NH + j];

#pragma unroll
    for (int kk = 0; kk < K; kk += 16) {
        float4 xv0 = xr4[kk / 4 + 0];
        float4 xv1 = xr4[kk / 4 + 1];
        float4 xv2 = xr4[kk / 4 + 2];
        float4 xv3 = xr4[kk / 4 + 3];
        float xs[16] = {xv0.x, xv0.y, xv0.z, xv0.w,
                        xv1.x, xv1.y, xv1.z, xv1.w,
                        xv2.x, xv2.y, xv2.z, xv2.w,
                        xv3.x, xv3.y, xv3.z, xv3.w};
        if (INAFF) {
#pragma unroll
            for (int i = 0; i < 16; i++) {
                xs[i] = fmaf(xs[i], as_[kk + i], cs_[kk + i]);
                if (INRELU) xs[i] = fmaxf(xs[i], 0.0f);
            }
        }
#pragma unroll
        for (int i = 0; i < 16; i++) {
            float xk = xs[i];
            const float* wr = Ws + (kk + i) * NOUT + half * NH;
#pragma unroll
            for (int j = 0; j < NH; j += 4) {
                float4 w = *(const float4*)(wr + j);
                acc[j + 0] = fmaf(xk, w.x, acc[j + 0]);
                acc[j + 1] = fmaf(xk, w.y, acc[j + 1]);
                acc[j + 2] = fmaf(xk, w.z, acc[j + 2]);
                acc[j + 3] = fmaf(xk, w.w, acc[j + 3]);
            }
        }
    }

    float4* o4 = (float4*)(out + (long long)row * NOUT + half * NH);
#pragma unroll
    for (int j = 0; j < NH; j += 4) {
        float4 v = make_float4(acc[j], acc[j + 1], acc[j + 2], acc[j + 3]);
        if (EPI == 1) {
            v.x = fmaxf(v.x, 0.0f); v.y = fmaxf(v.y, 0.0f);
            v.z = fmaxf(v.z, 0.0f); v.w = fmaxf(v.w, 0.0f);
        }
        o4[j / 4] = v;
    }
}

// ---------------- CSR gather: agg[n] = sum_e coef*t[src] + t[n]*dinv^2 + bias ----------------
__global__ void __launch_bounds__(256)
gather64_kernel(const float* __restrict__ bias)
{
    int n = blockIdx.x * 8 + (threadIdx.x >> 5);
    if (n >= NN) return;
    int lane = threadIdx.x & 31;

    int e = g_start[n], e1 = g_start[n + 1];
    const float2* T2 = (const float2*)g_t;

    float a0 = 0.0f, a1 = 0.0f;
    for (; e + 8 <= e1; e += 8) {
        int2 p[8];
#pragma unroll
        for (int q = 0; q < 8; q++) p[q] = g_csr[e + q];
        float2 v[8];
#pragma unroll
        for (int q = 0; q < 8; q++) v[q] = T2[p[q].x * 32 + lane];
#pragma unroll
        for (int q = 0; q < 8; q++) {
            float c = __int_as_float(p[q].y);
            a0 = fmaf(c, v[q].x, a0);
            a1 = fmaf(c, v[q].y, a1);
        }
    }
    for (; e < e1; e++) {
        int2 p = g_csr[e];
        float2 v = T2[p.x * 32 + lane];
        float c = __int_as_float(p.y);
        a0 = fmaf(c, v.x, a0); a1 = fmaf(c, v.y, a1);
    }

    float dv = g_dinv[n], d2 = dv * dv;
    float2 sv = T2[n * 32 + lane];
    a0 = fmaf(sv.x, d2, a0) + bias[2 * lane];
    a1 = fmaf(sv.y, d2, a1) + bias[2 * lane + 1];
    ((float2*)g_agg)[n * 32 + lane] = make_float2(a0, a1);
}

__global__ void __launch_bounds__(256)
gather32_kernel(const float* __restrict__ bias)
{
    int n = blockIdx.x * 8 + (threadIdx.x >> 5);
    if (n >= NN) return;
    int lane = threadIdx.x & 31;

    int e = g_start[n], e1 = g_start[n + 1];
    const float* T = g_t;

    float a0 = 0.0f;
    for (; e + 8 <= e1; e += 8) {
        int2 p[8];
#pragma unroll
        for (int q = 0; q < 8; q++) p[q] = g_csr[e + q];
        float v[8];
#pragma unroll
        for (int q = 0; q < 8; q++) v[q] = T[p[q].x * 32 + lane];
#pragma unroll
        for (int q = 0; q < 8; q++)
            a0 = fmaf(__int_as_float(p[q].y), v[q], a0);
    }
    for (; e < e1; e++) {
        int2 p = g_csr[e];
        a0 = fmaf(__int_as_float(p.y), T[p.x * 32 + lane], a0);
    }

    float dv = g_dinv[n], d2 = dv * dv;
    a0 = fmaf(T[n * 32 + lane], d2, a0) + bias[lane];
    g_agg[n * 32 + lane] = a0;
}

// ---------------- BN statistics (column sum / sumsq) ----------------
template<int C>
__global__ void __launch_bounds__(256)
bnstats_kernel(const float* __restrict__ x, int n, float* __restrict__ stats)
{
    const int BLK = 256;
    const int GR = BLK / C;
    int col = threadIdx.x & (C - 1);
    int grp = threadIdx.x / C;

    float s = 0.0f, s2 = 0.0f;
    for (int r = blockIdx.x * GR + grp; r < n; r += gridDim.x * GR) {
        float v = x[(long long)r * C + col];
        s += v;
        s2 = fmaf(v, v, s2);
    }
    __shared__ float sh0[BLK], sh1[BLK];
    sh0[threadIdx.x] = s;
    sh1[threadIdx.x] = s2;
    __syncthreads();
    if (grp == 0) {
#pragma unroll
        for (int g = 1; g < GR; g++) {
            s  += sh0[g * C + col];
            s2 += sh1[g * C + col];
        }
        atomicAdd(&stats[col], s);
        atomicAdd(&stats[64 + col], s2);
    }
}

// Final: BN params inline + row L2 normalize. Warp per row (lane == column).
__global__ void __launch_bounds__(256)
final_kernel(const float* __restrict__ stats, const float* __restrict__ gamma,
             const float* __restrict__ beta, float* __restrict__ out, int n)
{
    int t = blockIdx.x * blockDim.x + threadIdx.x;
    int row = t >> 5, lane = t & 31;
    if (row >= n) return;
    float s = stats[lane], s2 = stats[64 + lane];
    float mu = s * INVN;
    float var = fmaxf(s2 * INVN - mu * mu, 0.0f);
    float a = rsqrtf(var + BN_EPS) * gamma[lane];
    float c = fmaf(-mu, a, beta[lane]);
    float v = fmaf(g_agg[(long long)row * 32 + lane], a, c);
    float ss = v * v;
#pragma unroll
    for (int o = 16; o; o >>= 1) ss += __shfl_xor_sync(0xFFFFFFFFu, ss, o);
    out[(long long)row * 32 + lane] = v / fmaxf(sqrtf(ss), L2_EPS);
}

// ---------------- launch ----------------
extern "C" void kernel_launch(void* const* d_in, const int* in_sizes, int n_in,
                              void* d_out, int out_size)
{
    const float* x  = (const float*)d_in[0];
    const int*   ew = (const int*)d_in[1];
    const float* ne_w1 = (const float*)d_in[2];
    const float* ne_b1 = (const float*)d_in[3];
    const float* ne_g  = (const float*)d_in[4];
    const float* ne_be = (const float*)d_in[5];
    const float* ne_w2 = (const float*)d_in[6];
    const float* ne_b2 = (const float*)d_in[7];
    const float* c1_w = (const float*)d_in[8];
    const float* c1_b = (const float*)d_in[9];
    const float* g1   = (const float*)d_in[10];
    const float* be1  = (const float*)d_in[11];
    const float* c2_w = (const float*)d_in[12];
    const float* c2_b = (const float*)d_in[13];
    const float* g2   = (const float*)d_in[14];
    const float* be2  = (const float*)d_in[15];
    const float* c3_w = (const float*)d_in[16];
    const float* c3_b = (const float*)d_in[17];
    const float* g3   = (const float*)d_in[18];
    const float* be3  = (const float*)d_in[19];
    float* out = (float*)d_out;

    int ne = in_sizes[1] / 2;
    if (ne > MAXE) ne = MAXE;

    const int NB = (NN + 255) / 256;
    const int EB = (ne + 255) / 256;
    const int GB = (NN + 63) / 64;
    const int WB = (NN + 7) / 8;

    float* dT;   cudaGetSymbolAddress((void**)&dT,   g_t);
    float* dAgg; cudaGetSymbolAddress((void**)&dAgg, g_agg);
    float* dH;   cudaGetSymbolAddress((void**)&dH,   g_h);
    float* dS;   cudaGetSymbolAddress((void**)&dS,   g_stats4);
    float* sA = dS, *sB = dS + 128, *sC = dS + 256, *sD = dS + 384;

    static cudaStream_t s1 = nullptr;
    static cudaEvent_t ev0 = nullptr, ev1 = nullptr;
    if (!s1) {
        cudaStreamCreateWithFlags(&s1, cudaStreamNonBlocking);
        cudaEventCreateWithFlags(&ev0, cudaEventDisableTiming);
        cudaEventCreateWithFlags(&ev1, cudaEventDisableTiming);
    }

    // ---- init + dtype detect (main stream)
    init_kernel<<<NB, 256>>>();
    detect_kernel<<<1, 256>>>(ew, ne);
    cudaEventRecord(ev0, 0);

    // ---- CSR build on side stream (overlaps encoder)
    cudaStreamWaitEvent(s1, ev0, 0);
    deg_kernel<<<EB, 256, 0, s1>>>(ew, ne);
    bsum_kernel<<<SBLKS, SCHUNK, 0, s1>>>();
    bscan_kernel<<<1, 256, 0, s1>>>();
    expand_kernel<<<SBLKS, SCHUNK, 0, s1>>>();
    place_kernel<<<EB, 256, 0, s1>>>(ew, ne);
    cudaEventRecord(ev1, s1);

    // ---- node encoder on main stream
    gemm_kernel<32, 64, 1, false, false><<<GB, 128>>>(x, ne_w1, ne_b1, dT, NN, nullptr, nullptr, nullptr);
    bnstats_kernel<64><<<256, 256>>>(dT, NN, sA);
    gemm_kernel<64, 64, 0, true, false><<<GB, 128>>>(dT, ne_w2, ne_b2, dH, NN, sA, ne_g, ne_be);

    // join: conv layers need the CSR
    cudaStreamWaitEvent(0, ev1, 0);

    // ---- conv layer 1
    gemm_kernel<64, 64, 2, false, false><<<GB, 128>>>(dH, c1_w, c1_b, dT, NN, nullptr, nullptr, nullptr);
    gather64_kernel<<<WB, 256>>>(c1_b);
    bnstats_kernel<64><<<256, 256>>>(dAgg, NN, sB);

    // ---- conv layer 2 (BN+relu folded into GEMM input)
    gemm_kernel<64, 64, 2, true, true><<<GB, 128>>>(dAgg, c2_w, c2_b, dT, NN, sB, g1, be1);
    gather64_kernel<<<WB, 256>>>(c2_b);
    bnstats_kernel<64><<<256, 256>>>(dAgg, NN, sC);

    // ---- conv layer 3 (out=32)
    gemm_kernel<64, 32, 2, true, true><<<GB, 128>>>(dAgg, c3_w, c3_b, dT, NN, sC, g2, be2);
    gather32_kernel<<<WB, 256>>>(c3_b);
    bnstats_kernel<32><<<256, 256>>>(dAgg, NN, sD);

    // ---- final BN + L2 normalize
    final_kernel<<<(NN * 32 + 255) / 256, 256>>>(sD, g3, be3, out, NN);
}

// round 8
// speedup vs baseline: 1.4513x; 1.0766x over previous
#include <cuda_runtime.h>
#include <math.h>

#define NN 50000
#define MAXE 1700000
#define BN_EPS 1e-5f
#define L2_EPS 1e-12f
#define INVN (1.0f / 50000.0f)

#define SCHUNK 256
#define SBLKS ((NN + SCHUNK - 1) / SCHUNK)   // 196

// ---------------- scratch (static device globals; no allocation) ----------------
__device__ float g_dinv[NN];                       // rsqrt(degree+1)
__device__ __align__(16) float g_t[NN * 64];       // t = h @ W (pre-aggregation)
__device__ __align__(16) float g_agg[NN * 64];     // aggregation result
__device__ __align__(16) float g_h[NN * 64];       // encoder output
__device__ int   g_degcnt[NN];                     // in-degree (no self loop)
__device__ int   g_start[NN + 1];                  // CSR row starts
__device__ int   g_cursor[NN];                     // placement cursors
__device__ int   g_bsum[SBLKS];                    // per-block degree sums
__device__ int   g_boff[SBLKS];                    // exclusive block offsets
__device__ __align__(8) int2 g_csr[MAXE];          // {src, coef bits} grouped by dst
__device__ float g_stats4[4 * 128];                // 4 BN stat slots
__device__ int   g_not64;                          // 1 if edge_index is int32 layout

// ---------------- init: zero degcnt + stats; block 0 also probes dtype ----------------
__global__ void init_kernel(const int* __restrict__ w, int ne) {
    int i = blockIdx.x * blockDim.x + threadIdx.x;
    if (i < NN) g_degcnt[i] = 0;
    if (i < 512) g_stats4[i] = 0.0f;
    if (blockIdx.x == 0) {
        // dtype probe: int64 values < 2^31 have zero odd words
        int nz = 0;
        for (int k = 2 * threadIdx.x + 1; k < 2048 && k < 2 * ne; k += 512)
            nz |= (w[k] != 0);
        if (nz) atomicExch(&g_not64, 1);
    }
}

// in-degree histogram, 4 edges per thread
__global__ void deg_kernel(const int* __restrict__ w, int ne) {
    int base = (blockIdx.x * blockDim.x + threadIdx.x) * 4;
    if (base >= ne) return;
    int lim = min(4, ne - base);
    if (g_not64) {
        const int* dstp = w + ne + base;
#pragma unroll
        for (int q = 0; q < 4; q++)
            if (q < lim) atomicAdd(&g_degcnt[dstp[q]], 1);
    } else {
        const int* dstp = w + 2 * (ne + base);
#pragma unroll
        for (int q = 0; q < 4; q++)
            if (q < lim) atomicAdd(&g_degcnt[dstp[2 * q]], 1);
    }
}

// ---------------- decomposed scan ----------------
__global__ void __launch_bounds__(SCHUNK)
bsum_kernel() {
    int i = blockIdx.x * SCHUNK + threadIdx.x;
    int v = (i < NN) ? g_degcnt[i] : 0;
#pragma unroll
    for (int o = 16; o; o >>= 1) v += __shfl_xor_sync(0xFFFFFFFFu, v, o);
    __shared__ int ws[8];
    if ((threadIdx.x & 31) == 0) ws[threadIdx.x >> 5] = v;
    __syncthreads();
    if (threadIdx.x == 0) {
        int s = 0;
#pragma unroll
        for (int k = 0; k < 8; k++) s += ws[k];
        g_bsum[blockIdx.x] = s;
    }
}

__global__ void __launch_bounds__(256)
bscan_kernel() {
    int t = threadIdx.x;
    int v = (t < SBLKS) ? g_bsum[t] : 0;
    int lane = t & 31, warp = t >> 5;
    int x = v;
#pragma unroll
    for (int o = 1; o < 32; o <<= 1) {
        int y = __shfl_up_sync(0xFFFFFFFFu, x, o);
        if (lane >= o) x += y;
    }
    __shared__ int wsum[8];
    if (lane == 31) wsum[warp] = x;
    __syncthreads();
    if (warp == 0) {
        int w = (lane < 8) ? wsum[lane] : 0;
#pragma unroll
        for (int o = 1; o < 8; o <<= 1) {
            int y = __shfl_up_sync(0xFFFFFFFFu, w, o);
            if (lane >= o) w += y;
        }
        if (lane < 8) wsum[lane] = w;
    }
    __syncthreads();
    int incl = x + (warp ? wsum[warp - 1] : 0);
    if (t < SBLKS) g_boff[t] = incl - v;
    if (t == SBLKS - 1) g_start[NN] = incl;
}

__global__ void __launch_bounds__(SCHUNK)
expand_kernel() {
    int i = blockIdx.x * SCHUNK + threadIdx.x;
    int v = (i < NN) ? g_degcnt[i] : 0;
    int lane = threadIdx.x & 31, warp = threadIdx.x >> 5;
    int x = v;
#pragma unroll
    for (int o = 1; o < 32; o <<= 1) {
        int y = __shfl_up_sync(0xFFFFFFFFu, x, o);
        if (lane >= o) x += y;
    }
    __shared__ int wsum[8];
    if (lane == 31) wsum[warp] = x;
    __syncthreads();
    if (warp == 0) {
        int w = (lane < 8) ? wsum[lane] : 0;
#pragma unroll
        for (int o = 1; o < 8; o <<= 1) {
            int y = __shfl_up_sync(0xFFFFFFFFu, w, o);
            if (lane >= o) w += y;
        }
        if (lane < 8) wsum[lane] = w;
    }
    __syncthreads();
    int excl = x - v + (warp ? wsum[warp - 1] : 0) + g_boff[blockIdx.x];
    if (i < NN) {
        g_start[i] = excl;
        g_cursor[i] = excl;
        g_dinv[i] = rsqrtf((float)v + 1.0f);
    }
}

// place edges into CSR bins, 4 edges per thread
__global__ void place_kernel(const int* __restrict__ w, int ne) {
    int base = (blockIdx.x * blockDim.x + threadIdx.x) * 4;
    if (base >= ne) return;
    int lim = min(4, ne - base);
    int n64 = !g_not64;
#pragma unroll
    for (int q = 0; q < 4; q++) {
        if (q >= lim) break;
        int e = base + q;
        int s, d;
        if (n64) { s = w[2 * e]; d = w[2 * (ne + e)]; }
        else     { s = w[e];     d = w[ne + e]; }
        float cf = g_dinv[s] * g_dinv[d];
        int pos = atomicAdd(&g_cursor[d], 1);
        g_csr[pos] = make_int2(s, __float_as_int(cf));
    }
}

// ---------------- GEMM (2 threads per row; half = tid>>6 owns NOUT/2 cols) ----------------
template<int K, int NOUT, int EPI, bool INAFF, bool INRELU>
__global__ void __launch_bounds__(128)
gemm_kernel(const float* __restrict__ in, const float* __restrict__ W,
            const float* __restrict__ bias, float* __restrict__ out, int n,
            const float* __restrict__ stats, const float* __restrict__ gamma,
            const float* __restrict__ beta)
{
    const int NH = NOUT / 2;
    __shared__ float Ws[K * NOUT];
    __shared__ float bs[NOUT];
    __shared__ float as_[64], cs_[64];

    for (int i = threadIdx.x; i < K * NOUT; i += 128) Ws[i] = W[i];
    if (EPI != 2 && threadIdx.x < NOUT) bs[threadIdx.x] = bias[threadIdx.x];
    if (INAFF && threadIdx.x < K) {
        int t = threadIdx.x;
        float s = stats[t], s2 = stats[64 + t];
        float mu = s * INVN;
        float var = fmaxf(s2 * INVN - mu * mu, 0.0f);
        float a = rsqrtf(var + BN_EPS) * gamma[t];
        as_[t] = a;
        cs_[t] = fmaf(-mu, a, beta[t]);
    }
    __syncthreads();

    int row  = blockIdx.x * 64 + (threadIdx.x & 63);
    int half = threadIdx.x >> 6;
    if (row >= n) return;

    const float4* xr4 = (const float4*)(in + (long long)row * K);

    float acc[NH];
#pragma unroll
    for (int j = 0; j < NH; j++) acc[j] = (EPI == 2) ? 0.0f : bs[half * NH + j];

#pragma unroll
    for (int kk = 0; kk < K; kk += 16) {
        float4 xv0 = xr4[kk / 4 + 0];
        float4 xv1 = xr4[kk / 4 + 1];
        float4 xv2 = xr4[kk / 4 + 2];
        float4 xv3 = xr4[kk / 4 + 3];
        float xs[16] = {xv0.x, xv0.y, xv0.z, xv0.w,
                        xv1.x, xv1.y, xv1.z, xv1.w,
                        xv2.x, xv2.y, xv2.z, xv2.w,
                        xv3.x, xv3.y, xv3.z, xv3.w};
        if (INAFF) {
#pragma unroll
            for (int i = 0; i < 16; i++) {
                xs[i] = fmaf(xs[i], as_[kk + i], cs_[kk + i]);
                if (INRELU) xs[i] = fmaxf(xs[i], 0.0f);
            }
        }
#pragma unroll
        for (int i = 0; i < 16; i++) {
            float xk = xs[i];
            const float* wr = Ws + (kk + i) * NOUT + half * NH;
#pragma unroll
            for (int j = 0; j < NH; j += 4) {
                float4 w = *(const float4*)(wr + j);
                acc[j + 0] = fmaf(xk, w.x, acc[j + 0]);
                acc[j + 1] = fmaf(xk, w.y, acc[j + 1]);
                acc[j + 2] = fmaf(xk, w.z, acc[j + 2]);
                acc[j + 3] = fmaf(xk, w.w, acc[j + 3]);
            }
        }
    }

    float4* o4 = (float4*)(out + (long long)row * NOUT + half * NH);
#pragma unroll
    for (int j = 0; j < NH; j += 4) {
        float4 v = make_float4(acc[j], acc[j + 1], acc[j + 2], acc[j + 3]);
        if (EPI == 1) {
            v.x = fmaxf(v.x, 0.0f); v.y = fmaxf(v.y, 0.0f);
            v.z = fmaxf(v.z, 0.0f); v.w = fmaxf(v.w, 0.0f);
        }
        o4[j / 4] = v;
    }
}

// ---------------- CSR gather + fused BN stats ----------------
// agg[n] = sum_e coef*t[src] + t[n]*dinv^2 + bias; block covers 8 nodes exactly.
__global__ void __launch_bounds__(256)
gather64_kernel(const float* __restrict__ bias, float* __restrict__ stats)
{
    __shared__ float sh[8][64];
    int warp = threadIdx.x >> 5;
    int lane = threadIdx.x & 31;
    int n = blockIdx.x * 8 + warp;

    float a0 = 0.0f, a1 = 0.0f;
    if (n < NN) {
        int e = g_start[n], e1 = g_start[n + 1];
        const float2* T2 = (const float2*)g_t;
        for (; e + 8 <= e1; e += 8) {
            int2 p[8];
#pragma unroll
            for (int q = 0; q < 8; q++) p[q] = g_csr[e + q];
            float2 v[8];
#pragma unroll
            for (int q = 0; q < 8; q++) v[q] = T2[p[q].x * 32 + lane];
#pragma unroll
            for (int q = 0; q < 8; q++) {
                float c = __int_as_float(p[q].y);
                a0 = fmaf(c, v[q].x, a0);
                a1 = fmaf(c, v[q].y, a1);
            }
        }
        for (; e < e1; e++) {
            int2 p = g_csr[e];
            float2 v = T2[p.x * 32 + lane];
            float c = __int_as_float(p.y);
            a0 = fmaf(c, v.x, a0); a1 = fmaf(c, v.y, a1);
        }
        float dv = g_dinv[n], d2 = dv * dv;
        float2 sv = T2[n * 32 + lane];
        a0 = fmaf(sv.x, d2, a0) + bias[2 * lane];
        a1 = fmaf(sv.y, d2, a1) + bias[2 * lane + 1];
        ((float2*)g_agg)[n * 32 + lane] = make_float2(a0, a1);
    }
    sh[warp][2 * lane]     = a0;
    sh[warp][2 * lane + 1] = a1;
    __syncthreads();
    if (threadIdx.x < 64) {
        int c = threadIdx.x;
        float s = 0.0f, s2 = 0.0f;
#pragma unroll
        for (int wq = 0; wq < 8; wq++) {
            float v = sh[wq][c];
            s += v;
            s2 = fmaf(v, v, s2);
        }
        atomicAdd(&stats[c], s);
        atomicAdd(&stats[64 + c], s2);
    }
}

__global__ void __launch_bounds__(256)
gather32_kernel(const float* __restrict__ bias, float* __restrict__ stats)
{
    __shared__ float sh[8][32];
    int warp = threadIdx.x >> 5;
    int lane = threadIdx.x & 31;
    int n = blockIdx.x * 8 + warp;

    float a0 = 0.0f;
    if (n < NN) {
        int e = g_start[n], e1 = g_start[n + 1];
        const float* T = g_t;
        for (; e + 8 <= e1; e += 8) {
            int2 p[8];
#pragma unroll
            for (int q = 0; q < 8; q++) p[q] = g_csr[e + q];
            float v[8];
#pragma unroll
            for (int q = 0; q < 8; q++) v[q] = T[p[q].x * 32 + lane];
#pragma unroll
            for (int q = 0; q < 8; q++)
                a0 = fmaf(__int_as_float(p[q].y), v[q], a0);
        }
        for (; e < e1; e++) {
            int2 p = g_csr[e];
            a0 = fmaf(__int_as_float(p.y), T[p.x * 32 + lane], a0);
        }
        float dv = g_dinv[n], d2 = dv * dv;
        a0 = fmaf(T[n * 32 + lane], d2, a0) + bias[lane];
        g_agg[n * 32 + lane] = a0;
    }
    sh[warp][lane] = a0;
    __syncthreads();
    if (threadIdx.x < 32) {
        int c = threadIdx.x;
        float s = 0.0f, s2 = 0.0f;
#pragma unroll
        for (int wq = 0; wq < 8; wq++) {
            float v = sh[wq][c];
            s += v;
            s2 = fmaf(v, v, s2);
        }
        atomicAdd(&stats[c], s);
        atomicAdd(&stats[64 + c], s2);
    }
}

// ---------------- BN statistics (encoder only) ----------------
template<int C>
__global__ void __launch_bounds__(256)
bnstats_kernel(const float* __restrict__ x, int n, float* __restrict__ stats)
{
    const int BLK = 256;
    const int GR = BLK / C;
    int col = threadIdx.x & (C - 1);
    int grp = threadIdx.x / C;

    float s = 0.0f, s2 = 0.0f;
    for (int r = blockIdx.x * GR + grp; r < n; r += gridDim.x * GR) {
        float v = x[(long long)r * C + col];
        s += v;
        s2 = fmaf(v, v, s2);
    }
    __shared__ float sh0[BLK], sh1[BLK];
    sh0[threadIdx.x] = s;
    sh1[threadIdx.x] = s2;
    __syncthreads();
    if (grp == 0) {
#pragma unroll
        for (int g = 1; g < GR; g++) {
            s  += sh0[g * C + col];
            s2 += sh1[g * C + col];
        }
        atomicAdd(&stats[col], s);
        atomicAdd(&stats[64 + col], s2);
    }
}

// Final: BN params inline + row L2 normalize. Warp per row (lane == column).
__global__ void __launch_bounds__(256)
final_kernel(const float* __restrict__ stats, const float* __restrict__ gamma,
             const float* __restrict__ beta, float* __restrict__ out, int n)
{
    int t = blockIdx.x * blockDim.x + threadIdx.x;
    int row = t >> 5, lane = t & 31;
    if (row >= n) return;
    float s = stats[lane], s2 = stats[64 + lane];
    float mu = s * INVN;
    float var = fmaxf(s2 * INVN - mu * mu, 0.0f);
    float a = rsqrtf(var + BN_EPS) * gamma[lane];
    float c = fmaf(-mu, a, beta[lane]);
    float v = fmaf(g_agg[(long long)row * 32 + lane], a, c);
    float ss = v * v;
#pragma unroll
    for (int o = 16; o; o >>= 1) ss += __shfl_xor_sync(0xFFFFFFFFu, ss, o);
    out[(long long)row * 32 + lane] = v / fmaxf(sqrtf(ss), L2_EPS);
}

// ---------------- launch ----------------
extern "C" void kernel_launch(void* const* d_in, const int* in_sizes, int n_in,
                              void* d_out, int out_size)
{
    const float* x  = (const float*)d_in[0];
    const int*   ew = (const int*)d_in[1];
    const float* ne_w1 = (const float*)d_in[2];
    const float* ne_b1 = (const float*)d_in[3];
    const float* ne_g  = (const float*)d_in[4];
    const float* ne_be = (const float*)d_in[5];
    const float* ne_w2 = (const float*)d_in[6];
    const float* ne_b2 = (const float*)d_in[7];
    const float* c1_w = (const float*)d_in[8];
    const float* c1_b = (const float*)d_in[9];
    const float* g1   = (const float*)d_in[10];
    const float* be1  = (const float*)d_in[11];
    const float* c2_w = (const float*)d_in[12];
    const float* c2_b = (const float*)d_in[13];
    const float* g2   = (const float*)d_in[14];
    const float* be2  = (const float*)d_in[15];
    const float* c3_w = (const float*)d_in[16];
    const float* c3_b = (const float*)d_in[17];
    const float* g3   = (const float*)d_in[18];
    const float* be3  = (const float*)d_in[19];
    float* out = (float*)d_out;

    int ne = in_sizes[1] / 2;
    if (ne > MAXE) ne = MAXE;

    const int NB = (NN + 255) / 256;
    const int E4B = (ne / 4 + 256) / 256;   // 4-edges-per-thread blocks (covers tail)
    const int GB = (NN + 63) / 64;
    const int WB = (NN + 7) / 8;

    float* dT;   cudaGetSymbolAddress((void**)&dT,   g_t);
    float* dAgg; cudaGetSymbolAddress((void**)&dAgg, g_agg);
    float* dH;   cudaGetSymbolAddress((void**)&dH,   g_h);
    float* dS;   cudaGetSymbolAddress((void**)&dS,   g_stats4);
    float* sA = dS, *sB = dS + 128, *sC = dS + 256, *sD = dS + 384;

    static cudaStream_t s1 = nullptr;
    static cudaEvent_t ev0 = nullptr, ev1 = nullptr;
    if (!s1) {
        cudaStreamCreateWithFlags(&s1, cudaStreamNonBlocking);
        cudaEventCreateWithFlags(&ev0, cudaEventDisableTiming);
        cudaEventCreateWithFlags(&ev1, cudaEventDisableTiming);
    }

    // ---- init (zeros + dtype probe), then fork
    init_kernel<<<NB, 256>>>(ew, ne);
    cudaEventRecord(ev0, 0);

    // ---- CSR build on side stream (overlaps encoder)
    cudaStreamWaitEvent(s1, ev0, 0);
    deg_kernel<<<E4B, 256, 0, s1>>>(ew, ne);
    bsum_kernel<<<SBLKS, SCHUNK, 0, s1>>>();
    bscan_kernel<<<1, 256, 0, s1>>>();
    expand_kernel<<<SBLKS, SCHUNK, 0, s1>>>();
    place_kernel<<<E4B, 256, 0, s1>>>(ew, ne);
    cudaEventRecord(ev1, s1);

    // ---- node encoder on main stream
    gemm_kernel<32, 64, 1, false, false><<<GB, 128>>>(x, ne_w1, ne_b1, dT, NN, nullptr, nullptr, nullptr);
    bnstats_kernel<64><<<256, 256>>>(dT, NN, sA);
    gemm_kernel<64, 64, 0, true, false><<<GB, 128>>>(dT, ne_w2, ne_b2, dH, NN, sA, ne_g, ne_be);

    // join: conv layers need the CSR
    cudaStreamWaitEvent(0, ev1, 0);

    // ---- conv layer 1 (stats fused into gather)
    gemm_kernel<64, 64, 2, false, false><<<GB, 128>>>(dH, c1_w, c1_b, dT, NN, nullptr, nullptr, nullptr);
    gather64_kernel<<<WB, 256>>>(c1_b, sB);

    // ---- conv layer 2 (BN+relu folded into GEMM input; stats fused into gather)
    gemm_kernel<64, 64, 2, true, true><<<GB, 128>>>(dAgg, c2_w, c2_b, dT, NN, sB, g1, be1);
    gather64_kernel<<<WB, 256>>>(c2_b, sC);

    // ---- conv layer 3 (out=32; stats fused into gather)
    gemm_kernel<64, 32, 2, true, true><<<GB, 128>>>(dAgg, c3_w, c3_b, dT, NN, sC, g2, be2);
    gather32_kernel<<<WB, 256>>>(c3_b, sD);

    // ---- final BN + L2 normalize
    final_kernel<<<(NN * 32 + 255) / 256, 256>>>(sD, g3, be3, out, NN);
}

// round 9
// speedup vs baseline: 1.5351x; 1.0577x over previous
#include <cuda_runtime.h>
#include <cuda_fp16.h>
#include <math.h>

#define NN 50000
#define MAXE 1700000
#define BN_EPS 1e-5f
#define L2_EPS 1e-12f
#define INVN (1.0f / 50000.0f)

#define SCHUNK 256
#define SBLKS ((NN + SCHUNK - 1) / SCHUNK)   // 196

// ---------------- scratch (static device globals; no allocation) ----------------
__device__ float g_dinv[NN];                       // rsqrt(degree+1)
__device__ __align__(16) __half2 g_t[NN * 32];     // t = h @ W in fp16 (64 cols, or 32 cols @ stride 16)
__device__ __align__(16) float g_agg[NN * 64];     // aggregation result / encoder temp
__device__ __align__(16) float g_h[NN * 64];       // encoder output
__device__ int   g_degcnt[NN];                     // in-degree (no self loop)
__device__ int   g_start[NN + 1];                  // CSR row starts
__device__ int   g_cursor[NN];                     // placement cursors
__device__ int   g_bsum[SBLKS];                    // per-block degree sums
__device__ int   g_boff[SBLKS];                    // exclusive block offsets
__device__ __align__(8) int2 g_csr[MAXE];          // {src, coef bits} grouped by dst
__device__ float g_stats4[4 * 128];                // 4 BN stat slots
__device__ int   g_not64;                          // 1 if edge_index is int32 layout

// ---------------- init: zero degcnt + stats; block 0 also probes dtype ----------------
__global__ void init_kernel(const int* __restrict__ w, int ne) {
    int i = blockIdx.x * blockDim.x + threadIdx.x;
    if (i < NN) g_degcnt[i] = 0;
    if (i < 512) g_stats4[i] = 0.0f;
    if (blockIdx.x == 0) {
        int nz = 0;
        for (int k = 2 * threadIdx.x + 1; k < 2048 && k < 2 * ne; k += 512)
            nz |= (w[k] != 0);
        if (nz) atomicExch(&g_not64, 1);
    }
}

// in-degree histogram, 4 edges per thread
__global__ void deg_kernel(const int* __restrict__ w, int ne) {
    int base = (blockIdx.x * blockDim.x + threadIdx.x) * 4;
    if (base >= ne) return;
    int lim = min(4, ne - base);
    if (g_not64) {
        const int* dstp = w + ne + base;
#pragma unroll
        for (int q = 0; q < 4; q++)
            if (q < lim) atomicAdd(&g_degcnt[dstp[q]], 1);
    } else {
        const int* dstp = w + 2 * (ne + base);
#pragma unroll
        for (int q = 0; q < 4; q++)
            if (q < lim) atomicAdd(&g_degcnt[dstp[2 * q]], 1);
    }
}

// ---------------- decomposed scan ----------------
__global__ void __launch_bounds__(SCHUNK)
bsum_kernel() {
    int i = blockIdx.x * SCHUNK + threadIdx.x;
    int v = (i < NN) ? g_degcnt[i] : 0;
#pragma unroll
    for (int o = 16; o; o >>= 1) v += __shfl_xor_sync(0xFFFFFFFFu, v, o);
    __shared__ int ws[8];
    if ((threadIdx.x & 31) == 0) ws[threadIdx.x >> 5] = v;
    __syncthreads();
    if (threadIdx.x == 0) {
        int s = 0;
#pragma unroll
        for (int k = 0; k < 8; k++) s += ws[k];
        g_bsum[blockIdx.x] = s;
    }
}

__global__ void __launch_bounds__(256)
bscan_kernel() {
    int t = threadIdx.x;
    int v = (t < SBLKS) ? g_bsum[t] : 0;
    int lane = t & 31, warp = t >> 5;
    int x = v;
#pragma unroll
    for (int o = 1; o < 32; o <<= 1) {
        int y = __shfl_up_sync(0xFFFFFFFFu, x, o);
        if (lane >= o) x += y;
    }
    __shared__ int wsum[8];
    if (lane == 31) wsum[warp] = x;
    __syncthreads();
    if (warp == 0) {
        int w = (lane < 8) ? wsum[lane] : 0;
#pragma unroll
        for (int o = 1; o < 8; o <<= 1) {
            int y = __shfl_up_sync(0xFFFFFFFFu, w, o);
            if (lane >= o) w += y;
        }
        if (lane < 8) wsum[lane] = w;
    }
    __syncthreads();
    int incl = x + (warp ? wsum[warp - 1] : 0);
    if (t < SBLKS) g_boff[t] = incl - v;
    if (t == SBLKS - 1) g_start[NN] = incl;
}

__global__ void __launch_bounds__(SCHUNK)
expand_kernel() {
    int i = blockIdx.x * SCHUNK + threadIdx.x;
    int v = (i < NN) ? g_degcnt[i] : 0;
    int lane = threadIdx.x & 31, warp = threadIdx.x >> 5;
    int x = v;
#pragma unroll
    for (int o = 1; o < 32; o <<= 1) {
        int y = __shfl_up_sync(0xFFFFFFFFu, x, o);
        if (lane >= o) x += y;
    }
    __shared__ int wsum[8];
    if (lane == 31) wsum[warp] = x;
    __syncthreads();
    if (warp == 0) {
        int w = (lane < 8) ? wsum[lane] : 0;
#pragma unroll
        for (int o = 1; o < 8; o <<= 1) {
            int y = __shfl_up_sync(0xFFFFFFFFu, w, o);
            if (lane >= o) w += y;
        }
        if (lane < 8) wsum[lane] = w;
    }
    __syncthreads();
    int excl = x - v + (warp ? wsum[warp - 1] : 0) + g_boff[blockIdx.x];
    if (i < NN) {
        g_start[i] = excl;
        g_cursor[i] = excl;
        g_dinv[i] = rsqrtf((float)v + 1.0f);
    }
}

// place edges into CSR bins, 4 edges per thread
__global__ void place_kernel(const int* __restrict__ w, int ne) {
    int base = (blockIdx.x * blockDim.x + threadIdx.x) * 4;
    if (base >= ne) return;
    int lim = min(4, ne - base);
    int n64 = !g_not64;
#pragma unroll
    for (int q = 0; q < 4; q++) {
        if (q >= lim) break;
        int e = base + q;
        int s, d;
        if (n64) { s = w[2 * e]; d = w[2 * (ne + e)]; }
        else     { s = w[e];     d = w[ne + e]; }
        float cf = g_dinv[s] * g_dinv[d];
        int pos = atomicAdd(&g_cursor[d], 1);
        g_csr[pos] = make_int2(s, __float_as_int(cf));
    }
}

// ---------------- GEMM (2 threads per row; half = tid>>6 owns NOUT/2 cols) ----------------
// EPI: 0 = +bias store fp32 | 1 = +bias relu store fp32 | 2 = raw store AS FP16 into g_t
// INAFF: BN fold on input (params from stats/gamma/beta); INRELU: relu after affine
template<int K, int NOUT, int EPI, bool INAFF, bool INRELU>
__global__ void __launch_bounds__(128)
gemm_kernel(const float* __restrict__ in, const float* __restrict__ W,
            const float* __restrict__ bias, float* __restrict__ out, int n,
            const float* __restrict__ stats, const float* __restrict__ gamma,
            const float* __restrict__ beta)
{
    const int NH = NOUT / 2;
    __shared__ float Ws[K * NOUT];
    __shared__ float bs[NOUT];
    __shared__ float as_[64], cs_[64];

    for (int i = threadIdx.x; i < K * NOUT; i += 128) Ws[i] = W[i];
    if (EPI != 2 && threadIdx.x < NOUT) bs[threadIdx.x] = bias[threadIdx.x];
    if (INAFF && threadIdx.x < K) {
        int t = threadIdx.x;
        float s = stats[t], s2 = stats[64 + t];
        float mu = s * INVN;
        float var = fmaxf(s2 * INVN - mu * mu, 0.0f);
        float a = rsqrtf(var + BN_EPS) * gamma[t];
        as_[t] = a;
        cs_[t] = fmaf(-mu, a, beta[t]);
    }
    __syncthreads();

    int row  = blockIdx.x * 64 + (threadIdx.x & 63);
    int half = threadIdx.x >> 6;
    if (row >= n) return;

    const float4* xr4 = (const float4*)(in + (long long)row * K);

    float acc[NH];
#pragma unroll
    for (int j = 0; j < NH; j++) acc[j] = (EPI == 2) ? 0.0f : bs[half * NH + j];

#pragma unroll
    for (int kk = 0; kk < K; kk += 16) {
        float4 xv0 = xr4[kk / 4 + 0];
        float4 xv1 = xr4[kk / 4 + 1];
        float4 xv2 = xr4[kk / 4 + 2];
        float4 xv3 = xr4[kk / 4 + 3];
        float xs[16] = {xv0.x, xv0.y, xv0.z, xv0.w,
                        xv1.x, xv1.y, xv1.z, xv1.w,
                        xv2.x, xv2.y, xv2.z, xv2.w,
                        xv3.x, xv3.y, xv3.z, xv3.w};
        if (INAFF) {
#pragma unroll
            for (int i = 0; i < 16; i++) {
                xs[i] = fmaf(xs[i], as_[kk + i], cs_[kk + i]);
                if (INRELU) xs[i] = fmaxf(xs[i], 0.0f);
            }
        }
#pragma unroll
        for (int i = 0; i < 16; i++) {
            float xk = xs[i];
            const float* wr = Ws + (kk + i) * NOUT + half * NH;
#pragma unroll
            for (int j = 0; j < NH; j += 4) {
                float4 w = *(const float4*)(wr + j);
                acc[j + 0] = fmaf(xk, w.x, acc[j + 0]);
                acc[j + 1] = fmaf(xk, w.y, acc[j + 1]);
                acc[j + 2] = fmaf(xk, w.z, acc[j + 2]);
                acc[j + 3] = fmaf(xk, w.w, acc[j + 3]);
            }
        }
    }

    if (EPI == 2) {
        // fp16 store into g_t: row stride = NOUT/2 half2
        __half2 hbuf[NH / 2];
#pragma unroll
        for (int j = 0; j < NH; j += 2)
            hbuf[j / 2] = __floats2half2_rn(acc[j], acc[j + 1]);
        uint4* dst = (uint4*)((__half2*)g_t + (long long)row * (NOUT / 2) + half * (NH / 2));
        const uint4* src = (const uint4*)hbuf;
#pragma unroll
        for (int j = 0; j < NH / 8; j++) dst[j] = src[j];
    } else {
        float4* o4 = (float4*)(out + (long long)row * NOUT + half * NH);
#pragma unroll
        for (int j = 0; j < NH; j += 4) {
            float4 v = make_float4(acc[j], acc[j + 1], acc[j + 2], acc[j + 3]);
            if (EPI == 1) {
                v.x = fmaxf(v.x, 0.0f); v.y = fmaxf(v.y, 0.0f);
                v.z = fmaxf(v.z, 0.0f); v.w = fmaxf(v.w, 0.0f);
            }
            o4[j / 4] = v;
        }
    }
}

// ---------------- CSR gather (fp16 t) + fused BN stats ----------------
__global__ void __launch_bounds__(256)
gather64_kernel(const float* __restrict__ bias, float* __restrict__ stats)
{
    __shared__ float sh[8][64];
    int warp = threadIdx.x >> 5;
    int lane = threadIdx.x & 31;
    int n = blockIdx.x * 8 + warp;

    float a0 = 0.0f, a1 = 0.0f;
    if (n < NN) {
        int e = g_start[n], e1 = g_start[n + 1];
        const __half2* Th = g_t;
        for (; e + 8 <= e1; e += 8) {
            int2 p[8];
#pragma unroll
            for (int q = 0; q < 8; q++) p[q] = g_csr[e + q];
            __half2 v[8];
#pragma unroll
            for (int q = 0; q < 8; q++) v[q] = Th[p[q].x * 32 + lane];
#pragma unroll
            for (int q = 0; q < 8; q++) {
                float c = __int_as_float(p[q].y);
                float2 vf = __half22float2(v[q]);
                a0 = fmaf(c, vf.x, a0);
                a1 = fmaf(c, vf.y, a1);
            }
        }
        for (; e < e1; e++) {
            int2 p = g_csr[e];
            float2 vf = __half22float2(Th[p.x * 32 + lane]);
            float c = __int_as_float(p.y);
            a0 = fmaf(c, vf.x, a0); a1 = fmaf(c, vf.y, a1);
        }
        float dv = g_dinv[n], d2 = dv * dv;
        float2 sv = __half22float2(Th[n * 32 + lane]);
        a0 = fmaf(sv.x, d2, a0) + bias[2 * lane];
        a1 = fmaf(sv.y, d2, a1) + bias[2 * lane + 1];
        ((float2*)g_agg)[n * 32 + lane] = make_float2(a0, a1);
    }
    sh[warp][2 * lane]     = a0;
    sh[warp][2 * lane + 1] = a1;
    __syncthreads();
    if (threadIdx.x < 64) {
        int c = threadIdx.x;
        float s = 0.0f, s2 = 0.0f;
#pragma unroll
        for (int wq = 0; wq < 8; wq++) {
            float v = sh[wq][c];
            s += v;
            s2 = fmaf(v, v, s2);
        }
        atomicAdd(&stats[c], s);
        atomicAdd(&stats[64 + c], s2);
    }
}

__global__ void __launch_bounds__(256)
gather32_kernel(const float* __restrict__ bias, float* __restrict__ stats)
{
    __shared__ float sh[8][32];
    int warp = threadIdx.x >> 5;
    int lane = threadIdx.x & 31;
    int n = blockIdx.x * 8 + warp;

    float a0 = 0.0f;
    if (n < NN) {
        int e = g_start[n], e1 = g_start[n + 1];
        const __half* T = (const __half*)g_t;   // 32 cols per row
        for (; e + 8 <= e1; e += 8) {
            int2 p[8];
#pragma unroll
            for (int q = 0; q < 8; q++) p[q] = g_csr[e + q];
            __half v[8];
#pragma unroll
            for (int q = 0; q < 8; q++) v[q] = T[p[q].x * 32 + lane];
#pragma unroll
            for (int q = 0; q < 8; q++)
                a0 = fmaf(__int_as_float(p[q].y), __half2float(v[q]), a0);
        }
        for (; e < e1; e++) {
            int2 p = g_csr[e];
            a0 = fmaf(__int_as_float(p.y), __half2float(T[p.x * 32 + lane]), a0);
        }
        float dv = g_dinv[n], d2 = dv * dv;
        a0 = fmaf(__half2float(T[n * 32 + lane]), d2, a0) + bias[lane];
        g_agg[n * 32 + lane] = a0;
    }
    sh[warp][lane] = a0;
    __syncthreads();
    if (threadIdx.x < 32) {
        int c = threadIdx.x;
        float s = 0.0f, s2 = 0.0f;
#pragma unroll
        for (int wq = 0; wq < 8; wq++) {
            float v = sh[wq][c];
            s += v;
            s2 = fmaf(v, v, s2);
        }
        atomicAdd(&stats[c], s);
        atomicAdd(&stats[64 + c], s2);
    }
}

// ---------------- BN statistics (encoder only) ----------------
template<int C>
__global__ void __launch_bounds__(256)
bnstats_kernel(const float* __restrict__ x, int n, float* __restrict__ stats)
{
    const int BLK = 256;
    const int GR = BLK / C;
    int col = threadIdx.x & (C - 1);
    int grp = threadIdx.x / C;

    float s = 0.0f, s2 = 0.0f;
    for (int r = blockIdx.x * GR + grp; r < n; r += gridDim.x * GR) {
        float v = x[(long long)r * C + col];
        s += v;
        s2 = fmaf(v, v, s2);
    }
    __shared__ float sh0[BLK], sh1[BLK];
    sh0[threadIdx.x] = s;
    sh1[threadIdx.x] = s2;
    __syncthreads();
    if (grp == 0) {
#pragma unroll
        for (int g = 1; g < GR; g++) {
            s  += sh0[g * C + col];
            s2 += sh1[g * C + col];
        }
        atomicAdd(&stats[col], s);
        atomicAdd(&stats[64 + col], s2);
    }
}

// Final: BN params inline + row L2 normalize. Warp per row (lane == column).
__global__ void __launch_bounds__(256)
final_kernel(const float* __restrict__ stats, const float* __restrict__ gamma,
             const float* __restrict__ beta, float* __restrict__ out, int n)
{
    int t = blockIdx.x * blockDim.x + threadIdx.x;
    int row = t >> 5, lane = t & 31;
    if (row >= n) return;
    float s = stats[lane], s2 = stats[64 + lane];
    float mu = s * INVN;
    float var = fmaxf(s2 * INVN - mu * mu, 0.0f);
    float a = rsqrtf(var + BN_EPS) * gamma[lane];
    float c = fmaf(-mu, a, beta[lane]);
    float v = fmaf(g_agg[(long long)row * 32 + lane], a, c);
    float ss = v * v;
#pragma unroll
    for (int o = 16; o; o >>= 1) ss += __shfl_xor_sync(0xFFFFFFFFu, ss, o);
    out[(long long)row * 32 + lane] = v / fmaxf(sqrtf(ss), L2_EPS);
}

// ---------------- launch ----------------
extern "C" void kernel_launch(void* const* d_in, const int* in_sizes, int n_in,
                              void* d_out, int out_size)
{
    const float* x  = (const float*)d_in[0];
    const int*   ew = (const int*)d_in[1];
    const float* ne_w1 = (const float*)d_in[2];
    const float* ne_b1 = (const float*)d_in[3];
    const float* ne_g  = (const float*)d_in[4];
    const float* ne_be = (const float*)d_in[5];
    const float* ne_w2 = (const float*)d_in[6];
    const float* ne_b2 = (const float*)d_in[7];
    const float* c1_w = (const float*)d_in[8];
    const float* c1_b = (const float*)d_in[9];
    const float* g1   = (const float*)d_in[10];
    const float* be1  = (const float*)d_in[11];
    const float* c2_w = (const float*)d_in[12];
    const float* c2_b = (const float*)d_in[13];
    const float* g2   = (const float*)d_in[14];
    const float* be2  = (const float*)d_in[15];
    const float* c3_w = (const float*)d_in[16];
    const float* c3_b = (const float*)d_in[17];
    const float* g3   = (const float*)d_in[18];
    const float* be3  = (const float*)d_in[19];
    float* out = (float*)d_out;

    int ne = in_sizes[1] / 2;
    if (ne > MAXE) ne = MAXE;

    const int NB = (NN + 255) / 256;
    const int E4B = (ne / 4 + 256) / 256;
    const int GB = (NN + 63) / 64;
    const int WB = (NN + 7) / 8;

    float* dAgg; cudaGetSymbolAddress((void**)&dAgg, g_agg);
    float* dH;   cudaGetSymbolAddress((void**)&dH,   g_h);
    float* dS;   cudaGetSymbolAddress((void**)&dS,   g_stats4);
    float* sA = dS, *sB = dS + 128, *sC = dS + 256, *sD = dS + 384;

    static cudaStream_t s1 = nullptr;
    static cudaEvent_t ev0 = nullptr, ev1 = nullptr;
    if (!s1) {
        cudaStreamCreateWithFlags(&s1, cudaStreamNonBlocking);
        cudaEventCreateWithFlags(&ev0, cudaEventDisableTiming);
        cudaEventCreateWithFlags(&ev1, cudaEventDisableTiming);
    }

    // ---- init (zeros + dtype probe), then fork
    init_kernel<<<NB, 256>>>(ew, ne);
    cudaEventRecord(ev0, 0);

    // ---- CSR build on side stream (overlaps encoder + conv1 GEMM)
    cudaStreamWaitEvent(s1, ev0, 0);
    deg_kernel<<<E4B, 256, 0, s1>>>(ew, ne);
    bsum_kernel<<<SBLKS, SCHUNK, 0, s1>>>();
    bscan_kernel<<<1, 256, 0, s1>>>();
    expand_kernel<<<SBLKS, SCHUNK, 0, s1>>>();
    place_kernel<<<E4B, 256, 0, s1>>>(ew, ne);
    cudaEventRecord(ev1, s1);

    // ---- node encoder on main stream (uses g_agg as fp32 temp)
    gemm_kernel<32, 64, 1, false, false><<<GB, 128>>>(x, ne_w1, ne_b1, dAgg, NN, nullptr, nullptr, nullptr);
    bnstats_kernel<64><<<256, 256>>>(dAgg, NN, sA);
    gemm_kernel<64, 64, 0, true, false><<<GB, 128>>>(dAgg, ne_w2, ne_b2, dH, NN, sA, ne_g, ne_be);

    // ---- conv layer 1 GEMM (no CSR needed yet; extends side-chain shadow)
    gemm_kernel<64, 64, 2, false, false><<<GB, 128>>>(dH, c1_w, c1_b, nullptr, NN, nullptr, nullptr, nullptr);

    // join: gathers need the CSR
    cudaStreamWaitEvent(0, ev1, 0);

    gather64_kernel<<<WB, 256>>>(c1_b, sB);

    // ---- conv layer 2 (BN+relu folded into GEMM input; stats fused into gather)
    gemm_kernel<64, 64, 2, true, true><<<GB, 128>>>(dAgg, c2_w, c2_b, nullptr, NN, sB, g1, be1);
    gather64_kernel<<<WB, 256>>>(c2_b, sC);

    // ---- conv layer 3 (out=32)
    gemm_kernel<64, 32, 2, true, true><<<GB, 128>>>(dAgg, c3_w, c3_b, nullptr, NN, sC, g2, be2);
    gather32_kernel<<<WB, 256>>>(c3_b, sD);

    // ---- final BN + L2 normalize
    final_kernel<<<(NN * 32 + 255) / 256, 256>>>(sD, g3, be3, out, NN);
}

// round 10
// speedup vs baseline: 1.5934x; 1.0380x over previous
#include <cuda_runtime.h>
#include <cuda_fp16.h>
#include <math.h>

#define NN 50000
#define MAXE 1700000
#define BN_EPS 1e-5f
#define L2_EPS 1e-12f
#define INVN (1.0f / 50000.0f)

#define SCHUNK 256
#define SBLKS ((NN + SCHUNK - 1) / SCHUNK)   // 196
#define LMASK ((1u << 30) - 1u)

// ---------------- scratch (static device globals; no allocation) ----------------
__device__ float g_dinv[NN];                       // rsqrt(degree+1)
__device__ __align__(16) __half2 g_t[NN * 32];     // t = h @ W in fp16
__device__ __align__(16) float g_agg[NN * 64];     // aggregation result / encoder temp
__device__ __align__(16) float g_h[NN * 64];       // encoder output
__device__ int   g_degcnt[NN];                     // in-degree (no self loop)
__device__ int   g_start[NN + 1];                  // CSR row starts
__device__ int   g_cursor[NN];                     // placement cursors
__device__ unsigned int g_look[SBLKS];             // lookback word: 0 | (1<<30)|agg | (2<<30)|incl
__device__ __align__(8) int2 g_csr[MAXE];          // {src, coef bits} grouped by dst
__device__ float g_stats4[4 * 128];                // 4 BN stat slots
__device__ int   g_not64;                          // 1 if edge_index is int32 layout

// ---------------- init: zero degcnt + stats + lookback; block 0 probes dtype ----------------
__global__ void init_kernel(const int* __restrict__ w, int ne) {
    int i = blockIdx.x * blockDim.x + threadIdx.x;
    if (i < NN) g_degcnt[i] = 0;
    if (i < 512) g_stats4[i] = 0.0f;
    if (i < SBLKS) g_look[i] = 0u;
    if (blockIdx.x == 0) {
        int nz = 0;
        for (int k = 2 * threadIdx.x + 1; k < 2048 && k < 2 * ne; k += 512)
            nz |= (w[k] != 0);
        if (nz) atomicExch(&g_not64, 1);
    }
}

// in-degree histogram, 4 edges per thread
__global__ void deg_kernel(const int* __restrict__ w, int ne) {
    int base = (blockIdx.x * blockDim.x + threadIdx.x) * 4;
    if (base >= ne) return;
    int lim = min(4, ne - base);
    if (g_not64) {
        const int* dstp = w + ne + base;
#pragma unroll
        for (int q = 0; q < 4; q++)
            if (q < lim) atomicAdd(&g_degcnt[dstp[q]], 1);
    } else {
        const int* dstp = w + 2 * (ne + base);
#pragma unroll
        for (int q = 0; q < 4; q++)
            if (q < lim) atomicAdd(&g_degcnt[dstp[2 * q]], 1);
    }
}

// ---------------- single-pass decoupled-lookback scan ----------------
// All SBLKS blocks are co-resident, so spinning on predecessors is safe.
__global__ void __launch_bounds__(SCHUNK)
scan_lb_kernel() {
    int b = blockIdx.x;
    int i = b * SCHUNK + threadIdx.x;
    int v = (i < NN) ? g_degcnt[i] : 0;
    int lane = threadIdx.x & 31, warp = threadIdx.x >> 5;

    // block-local inclusive scan
    int x = v;
#pragma unroll
    for (int o = 1; o < 32; o <<= 1) {
        int y = __shfl_up_sync(0xFFFFFFFFu, x, o);
        if (lane >= o) x += y;
    }
    __shared__ int wsum[8];
    if (lane == 31) wsum[warp] = x;
    __syncthreads();
    if (warp == 0) {
        int w = (lane < 8) ? wsum[lane] : 0;
#pragma unroll
        for (int o = 1; o < 8; o <<= 1) {
            int y = __shfl_up_sync(0xFFFFFFFFu, w, o);
            if (lane >= o) w += y;
        }
        if (lane < 8) wsum[lane] = w;
    }
    __syncthreads();
    int incl_local = x + (warp ? wsum[warp - 1] : 0);
    int block_total = wsum[7];

    // thread 0: publish aggregate, look back, publish inclusive prefix
    __shared__ int s_prev;
    if (threadIdx.x == 0) {
        atomicExch(&g_look[b], (1u << 30) | (unsigned)block_total);
        int run = 0;
        for (int j = b - 1; j >= 0; ) {
            unsigned u = atomicAdd(&g_look[j], 0u);
            if (u == 0u) continue;                   // predecessor not ready yet
            if ((u >> 30) == 2u) { run += (int)(u & LMASK); break; }
            run += (int)(u & LMASK); j--;
        }
        atomicExch(&g_look[b], (2u << 30) | (unsigned)(run + block_total));
        s_prev = run;
    }
    __syncthreads();

    int excl = incl_local - v + s_prev;
    if (i < NN) {
        g_start[i] = excl;
        g_cursor[i] = excl;
        g_dinv[i] = rsqrtf((float)v + 1.0f);
        if (i == NN - 1) g_start[NN] = excl + v;
    }
}

// place edges into CSR bins, 4 edges per thread
__global__ void place_kernel(const int* __restrict__ w, int ne) {
    int base = (blockIdx.x * blockDim.x + threadIdx.x) * 4;
    if (base >= ne) return;
    int lim = min(4, ne - base);
    int n64 = !g_not64;
#pragma unroll
    for (int q = 0; q < 4; q++) {
        if (q >= lim) break;
        int e = base + q;
        int s, d;
        if (n64) { s = w[2 * e]; d = w[2 * (ne + e)]; }
        else     { s = w[e];     d = w[ne + e]; }
        float cf = g_dinv[s] * g_dinv[d];
        int pos = atomicAdd(&g_cursor[d], 1);
        g_csr[pos] = make_int2(s, __float_as_int(cf));
    }
}

// ---------------- GEMM (2 threads per row; half = tid>>6 owns NOUT/2 cols) ----------------
// EPI: 0 = +bias store fp32 | 1 = +bias relu store fp32 | 2 = raw store AS FP16 into g_t
// INAFF: BN fold on input; INRELU: relu after affine; STATS: fuse BN col-stats (EPI==1 only)
template<int K, int NOUT, int EPI, bool INAFF, bool INRELU, bool STATS>
__global__ void __launch_bounds__(128)
gemm_kernel(const float* __restrict__ in, const float* __restrict__ W,
            const float* __restrict__ bias, float* __restrict__ out, int n,
            const float* __restrict__ stats, const float* __restrict__ gamma,
            const float* __restrict__ beta, float* __restrict__ stats_out)
{
    const int NH = NOUT / 2;
    __shared__ float Ws[K * NOUT];
    __shared__ float bs[NOUT];
    __shared__ float as_[64], cs_[64];
    __shared__ float sv[STATS ? 64 * 65 : 1];

    for (int i = threadIdx.x; i < K * NOUT; i += 128) Ws[i] = W[i];
    if (EPI != 2 && threadIdx.x < NOUT) bs[threadIdx.x] = bias[threadIdx.x];
    if (INAFF && threadIdx.x < K) {
        int t = threadIdx.x;
        float s = stats[t], s2 = stats[64 + t];
        float mu = s * INVN;
        float var = fmaxf(s2 * INVN - mu * mu, 0.0f);
        float a = rsqrtf(var + BN_EPS) * gamma[t];
        as_[t] = a;
        cs_[t] = fmaf(-mu, a, beta[t]);
    }
    __syncthreads();

    int r    = threadIdx.x & 63;
    int row  = blockIdx.x * 64 + r;
    int half = threadIdx.x >> 6;
    bool valid = row < n;
    if (!STATS && !valid) return;
    int rowc = valid ? row : (n - 1);     // clamped for safe loads when STATS

    const float4* xr4 = (const float4*)(in + (long long)rowc * K);

    float acc[NH];
#pragma unroll
    for (int j = 0; j < NH; j++) acc[j] = (EPI == 2) ? 0.0f : bs[half * NH + j];

#pragma unroll
    for (int kk = 0; kk < K; kk += 16) {
        float4 xv0 = xr4[kk / 4 + 0];
        float4 xv1 = xr4[kk / 4 + 1];
        float4 xv2 = xr4[kk / 4 + 2];
        float4 xv3 = xr4[kk / 4 + 3];
        float xs[16] = {xv0.x, xv0.y, xv0.z, xv0.w,
                        xv1.x, xv1.y, xv1.z, xv1.w,
                        xv2.x, xv2.y, xv2.z, xv2.w,
                        xv3.x, xv3.y, xv3.z, xv3.w};
        if (INAFF) {
#pragma unroll
            for (int i = 0; i < 16; i++) {
                xs[i] = fmaf(xs[i], as_[kk + i], cs_[kk + i]);
                if (INRELU) xs[i] = fmaxf(xs[i], 0.0f);
            }
        }
#pragma unroll
        for (int i = 0; i < 16; i++) {
            float xk = xs[i];
            const float* wr = Ws + (kk + i) * NOUT + half * NH;
#pragma unroll
            for (int j = 0; j < NH; j += 4) {
                float4 w = *(const float4*)(wr + j);
                acc[j + 0] = fmaf(xk, w.x, acc[j + 0]);
                acc[j + 1] = fmaf(xk, w.y, acc[j + 1]);
                acc[j + 2] = fmaf(xk, w.z, acc[j + 2]);
                acc[j + 3] = fmaf(xk, w.w, acc[j + 3]);
            }
        }
    }

    if (EPI == 2) {
        __half2 hbuf[NH / 2];
#pragma unroll
        for (int j = 0; j < NH; j += 2)
            hbuf[j / 2] = __floats2half2_rn(acc[j], acc[j + 1]);
        uint4* dst = (uint4*)((__half2*)g_t + (long long)row * (NOUT / 2) + half * (NH / 2));
        const uint4* src = (const uint4*)hbuf;
#pragma unroll
        for (int j = 0; j < NH / 8; j++) dst[j] = src[j];
    } else {
        if (EPI == 1) {
#pragma unroll
            for (int j = 0; j < NH; j++) acc[j] = fmaxf(acc[j], 0.0f);
        }
        if (valid) {
            float4* o4 = (float4*)(out + (long long)row * NOUT + half * NH);
#pragma unroll
            for (int j = 0; j < NH; j += 4)
                o4[j / 4] = make_float4(acc[j], acc[j + 1], acc[j + 2], acc[j + 3]);
        }
        if (STATS) {
#pragma unroll
            for (int j = 0; j < NH; j++)
                sv[r * 65 + half * NH + j] = valid ? acc[j] : 0.0f;
            __syncthreads();
            if (threadIdx.x < NOUT) {
                int c = threadIdx.x;
                float s = 0.0f, s2 = 0.0f;
#pragma unroll
                for (int r2 = 0; r2 < 64; r2++) {
                    float v = sv[r2 * 65 + c];
                    s += v;
                    s2 = fmaf(v, v, s2);
                }
                atomicAdd(&stats_out[c], s);
                atomicAdd(&stats_out[64 + c], s2);
            }
        }
    }
}

// ---------------- CSR gather (fp16 t) + fused BN stats ----------------
__global__ void __launch_bounds__(256)
gather64_kernel(const float* __restrict__ bias, float* __restrict__ stats)
{
    __shared__ float sh[8][64];
    int warp = threadIdx.x >> 5;
    int lane = threadIdx.x & 31;
    int n = blockIdx.x * 8 + warp;

    float a0 = 0.0f, a1 = 0.0f;
    if (n < NN) {
        int e = g_start[n], e1 = g_start[n + 1];
        const __half2* Th = g_t;
        for (; e + 8 <= e1; e += 8) {
            int2 p[8];
#pragma unroll
            for (int q = 0; q < 8; q++) p[q] = g_csr[e + q];
            __half2 v[8];
#pragma unroll
            for (int q = 0; q < 8; q++) v[q] = Th[p[q].x * 32 + lane];
#pragma unroll
            for (int q = 0; q < 8; q++) {
                float c = __int_as_float(p[q].y);
                float2 vf = __half22float2(v[q]);
                a0 = fmaf(c, vf.x, a0);
                a1 = fmaf(c, vf.y, a1);
            }
        }
        for (; e < e1; e++) {
            int2 p = g_csr[e];
            float2 vf = __half22float2(Th[p.x * 32 + lane]);
            float c = __int_as_float(p.y);
            a0 = fmaf(c, vf.x, a0); a1 = fmaf(c, vf.y, a1);
        }
        float dv = g_dinv[n], d2 = dv * dv;
        float2 sv2 = __half22float2(Th[n * 32 + lane]);
        a0 = fmaf(sv2.x, d2, a0) + bias[2 * lane];
        a1 = fmaf(sv2.y, d2, a1) + bias[2 * lane + 1];
        ((float2*)g_agg)[n * 32 + lane] = make_float2(a0, a1);
    }
    sh[warp][2 * lane]     = a0;
    sh[warp][2 * lane + 1] = a1;
    __syncthreads();
    if (threadIdx.x < 64) {
        int c = threadIdx.x;
        float s = 0.0f, s2 = 0.0f;
#pragma unroll
        for (int wq = 0; wq < 8; wq++) {
            float v = sh[wq][c];
            s += v;
            s2 = fmaf(v, v, s2);
        }
        atomicAdd(&stats[c], s);
        atomicAdd(&stats[64 + c], s2);
    }
}

__global__ void __launch_bounds__(256)
gather32_kernel(const float* __restrict__ bias, float* __restrict__ stats)
{
    __shared__ float sh[8][32];
    int warp = threadIdx.x >> 5;
    int lane = threadIdx.x & 31;
    int n = blockIdx.x * 8 + warp;

    float a0 = 0.0f;
    if (n < NN) {
        int e = g_start[n], e1 = g_start[n + 1];
        const __half* T = (const __half*)g_t;   // 32 cols per row
        for (; e + 8 <= e1; e += 8) {
            int2 p[8];
#pragma unroll
            for (int q = 0; q < 8; q++) p[q] = g_csr[e + q];
            __half v[8];
#pragma unroll
            for (int q = 0; q < 8; q++) v[q] = T[p[q].x * 32 + lane];
#pragma unroll
            for (int q = 0; q < 8; q++)
                a0 = fmaf(__int_as_float(p[q].y), __half2float(v[q]), a0);
        }
        for (; e < e1; e++) {
            int2 p = g_csr[e];
            a0 = fmaf(__int_as_float(p.y), __half2float(T[p.x * 32 + lane]), a0);
        }
        float dv = g_dinv[n], d2 = dv * dv;
        a0 = fmaf(__half2float(T[n * 32 + lane]), d2, a0) + bias[lane];
        g_agg[n * 32 + lane] = a0;
    }
    sh[warp][lane] = a0;
    __syncthreads();
    if (threadIdx.x < 32) {
        int c = threadIdx.x;
        float s = 0.0f, s2 = 0.0f;
#pragma unroll
        for (int wq = 0; wq < 8; wq++) {
            float v = sh[wq][c];
            s += v;
            s2 = fmaf(v, v, s2);
        }
        atomicAdd(&stats[c], s);
        atomicAdd(&stats[64 + c], s2);
    }
}

// Final: BN params inline + row L2 normalize. Warp per row (lane == column).
__global__ void __launch_bounds__(256)
final_kernel(const float* __restrict__ stats, const float* __restrict__ gamma,
             const float* __restrict__ beta, float* __restrict__ out, int n)
{
    int t = blockIdx.x * blockDim.x + threadIdx.x;
    int row = t >> 5, lane = t & 31;
    if (row >= n) return;
    float s = stats[lane], s2 = stats[64 + lane];
    float mu = s * INVN;
    float var = fmaxf(s2 * INVN - mu * mu, 0.0f);
    float a = rsqrtf(var + BN_EPS) * gamma[lane];
    float c = fmaf(-mu, a, beta[lane]);
    float v = fmaf(g_agg[(long long)row * 32 + lane], a, c);
    float ss = v * v;
#pragma unroll
    for (int o = 16; o; o >>= 1) ss += __shfl_xor_sync(0xFFFFFFFFu, ss, o);
    out[(long long)row * 32 + lane] = v / fmaxf(sqrtf(ss), L2_EPS);
}

// ---------------- launch ----------------
extern "C" void kernel_launch(void* const* d_in, const int* in_sizes, int n_in,
                              void* d_out, int out_size)
{
    const float* x  = (const float*)d_in[0];
    const int*   ew = (const int*)d_in[1];
    const float* ne_w1 = (const float*)d_in[2];
    const float* ne_b1 = (const float*)d_in[3];
    const float* ne_g  = (const float*)d_in[4];
    const float* ne_be = (const float*)d_in[5];
    const float* ne_w2 = (const float*)d_in[6];
    const float* ne_b2 = (const float*)d_in[7];
    const float* c1_w = (const float*)d_in[8];
    const float* c1_b = (const float*)d_in[9];
    const float* g1   = (const float*)d_in[10];
    const float* be1  = (const float*)d_in[11];
    const float* c2_w = (const float*)d_in[12];
    const float* c2_b = (const float*)d_in[13];
    const float* g2   = (const float*)d_in[14];
    const float* be2  = (const float*)d_in[15];
    const float* c3_w = (const float*)d_in[16];
    const float* c3_b = (const float*)d_in[17];
    const float* g3   = (const float*)d_in[18];
    const float* be3  = (const float*)d_in[19];
    float* out = (float*)d_out;

    int ne = in_sizes[1] / 2;
    if (ne > MAXE) ne = MAXE;

    const int NB = (NN + 255) / 256;
    const int E4B = (ne / 4 + 256) / 256;
    const int GB = (NN + 63) / 64;
    const int WB = (NN + 7) / 8;

    float* dAgg; cudaGetSymbolAddress((void**)&dAgg, g_agg);
    float* dH;   cudaGetSymbolAddress((void**)&dH,   g_h);
    float* dS;   cudaGetSymbolAddress((void**)&dS,   g_stats4);
    float* sA = dS, *sB = dS + 128, *sC = dS + 256, *sD = dS + 384;

    static cudaStream_t s1 = nullptr;
    static cudaEvent_t ev0 = nullptr, ev1 = nullptr;
    if (!s1) {
        cudaStreamCreateWithFlags(&s1, cudaStreamNonBlocking);
        cudaEventCreateWithFlags(&ev0, cudaEventDisableTiming);
        cudaEventCreateWithFlags(&ev1, cudaEventDisableTiming);
    }

    // ---- init (zeros + dtype probe), then fork
    init_kernel<<<NB, 256>>>(ew, ne);
    cudaEventRecord(ev0, 0);

    // ---- CSR build on side stream (overlaps encoder + conv1 GEMM)
    cudaStreamWaitEvent(s1, ev0, 0);
    deg_kernel<<<E4B, 256, 0, s1>>>(ew, ne);
    scan_lb_kernel<<<SBLKS, SCHUNK, 0, s1>>>();
    place_kernel<<<E4B, 256, 0, s1>>>(ew, ne);
    cudaEventRecord(ev1, s1);

    // ---- node encoder on main stream (stats fused into GEMM-1 epilogue)
    gemm_kernel<32, 64, 1, false, false, true><<<GB, 128>>>(x, ne_w1, ne_b1, dAgg, NN, nullptr, nullptr, nullptr, sA);
    gemm_kernel<64, 64, 0, true, false, false><<<GB, 128>>>(dAgg, ne_w2, ne_b2, dH, NN, sA, ne_g, ne_be, nullptr);

    // ---- conv layer 1 GEMM (no CSR needed yet; extends side-chain shadow)
    gemm_kernel<64, 64, 2, false, false, false><<<GB, 128>>>(dH, c1_w, c1_b, nullptr, NN, nullptr, nullptr, nullptr, nullptr);

    // join: gathers need the CSR
    cudaStreamWaitEvent(0, ev1, 0);

    gather64_kernel<<<WB, 256>>>(c1_b, sB);

    // ---- conv layer 2 (BN+relu folded into GEMM input; stats fused into gather)
    gemm_kernel<64, 64, 2, true, true, false><<<GB, 128>>>(dAgg, c2_w, c2_b, nullptr, NN, sB, g1, be1, nullptr);
    gather64_kernel<<<WB, 256>>>(c2_b, sC);

    // ---- conv layer 3 (out=32)
    gemm_kernel<64, 32, 2, true, true, false><<<GB, 128>>>(dAgg, c3_w, c3_b, nullptr, NN, sC, g2, be2, nullptr);
    gather32_kernel<<<WB, 256>>>(c3_b, sD);

    // ---- final BN + L2 normalize
    final_kernel<<<(NN * 32 + 255) / 256, 256>>>(sD, g3, be3, out, NN);
}

// round 11
// speedup vs baseline: 1.6175x; 1.0151x over previous
#include <cuda_runtime.h>
#include <cuda_fp16.h>
#include <math.h>

#define NN 50000
#define MAXE 1700000
#define BN_EPS 1e-5f
#define L2_EPS 1e-12f
#define INVN (1.0f / 50000.0f)

#define SCHUNK 256
#define SBLKS ((NN + SCHUNK - 1) / SCHUNK)   // 196
#define LMASK ((1u << 30) - 1u)

// ---------------- scratch (static device globals; no allocation) ----------------
__device__ float g_dinv[NN];                       // rsqrt(degree+1)
__device__ __align__(16) __half2 g_t[NN * 32];     // t = h @ W in fp16
__device__ __align__(16) float g_agg[NN * 64];     // aggregation result / encoder temp
__device__ __align__(16) float g_h[NN * 64];       // encoder output
__device__ int   g_degcnt[NN];                     // in-degree (no self loop)
__device__ int   g_start[NN + 1];                  // CSR row starts
__device__ int   g_cursor[NN];                     // placement cursors
__device__ unsigned int g_look[SBLKS];             // lookback word
__device__ int   g_csr[MAXE];                      // src only (4B), grouped by dst
__device__ float g_stats4[4 * 128];                // 4 BN stat slots
__device__ int   g_not64;                          // 1 if edge_index is int32 layout

// ---------------- init: zero degcnt + stats + lookback; block 0 probes dtype ----------------
__global__ void init_kernel(const int* __restrict__ w, int ne) {
    int i = blockIdx.x * blockDim.x + threadIdx.x;
    if (i < NN) g_degcnt[i] = 0;
    if (i < 512) g_stats4[i] = 0.0f;
    if (i < SBLKS) g_look[i] = 0u;
    if (blockIdx.x == 0) {
        int nz = 0;
        for (int k = 2 * threadIdx.x + 1; k < 2048 && k < 2 * ne; k += 512)
            nz |= (w[k] != 0);
        if (nz) atomicExch(&g_not64, 1);
    }
}

// in-degree histogram, 4 edges per thread
__global__ void deg_kernel(const int* __restrict__ w, int ne) {
    int base = (blockIdx.x * blockDim.x + threadIdx.x) * 4;
    if (base >= ne) return;
    int lim = min(4, ne - base);
    if (g_not64) {
        const int* dstp = w + ne + base;
#pragma unroll
        for (int q = 0; q < 4; q++)
            if (q < lim) atomicAdd(&g_degcnt[dstp[q]], 1);
    } else {
        const int* dstp = w + 2 * (ne + base);
#pragma unroll
        for (int q = 0; q < 4; q++)
            if (q < lim) atomicAdd(&g_degcnt[dstp[2 * q]], 1);
    }
}

// ---------------- single-pass decoupled-lookback scan ----------------
__global__ void __launch_bounds__(SCHUNK)
scan_lb_kernel() {
    int b = blockIdx.x;
    int i = b * SCHUNK + threadIdx.x;
    int v = (i < NN) ? g_degcnt[i] : 0;
    int lane = threadIdx.x & 31, warp = threadIdx.x >> 5;

    int x = v;
#pragma unroll
    for (int o = 1; o < 32; o <<= 1) {
        int y = __shfl_up_sync(0xFFFFFFFFu, x, o);
        if (lane >= o) x += y;
    }
    __shared__ int wsum[8];
    if (lane == 31) wsum[warp] = x;
    __syncthreads();
    if (warp == 0) {
        int w = (lane < 8) ? wsum[lane] : 0;
#pragma unroll
        for (int o = 1; o < 8; o <<= 1) {
            int y = __shfl_up_sync(0xFFFFFFFFu, w, o);
            if (lane >= o) w += y;
        }
        if (lane < 8) wsum[lane] = w;
    }
    __syncthreads();
    int incl_local = x + (warp ? wsum[warp - 1] : 0);
    int block_total = wsum[7];

    __shared__ int s_prev;
    if (threadIdx.x == 0) {
        atomicExch(&g_look[b], (1u << 30) | (unsigned)block_total);
        int run = 0;
        for (int j = b - 1; j >= 0; ) {
            unsigned u = atomicAdd(&g_look[j], 0u);
            if (u == 0u) continue;
            if ((u >> 30) == 2u) { run += (int)(u & LMASK); break; }
            run += (int)(u & LMASK); j--;
        }
        atomicExch(&g_look[b], (2u << 30) | (unsigned)(run + block_total));
        s_prev = run;
    }
    __syncthreads();

    int excl = incl_local - v + s_prev;
    if (i < NN) {
        g_start[i] = excl;
        g_cursor[i] = excl;
        g_dinv[i] = rsqrtf((float)v + 1.0f);
        if (i == NN - 1) g_start[NN] = excl + v;
    }
}

// place edges into CSR bins (src only), 4 edges per thread
__global__ void place_kernel(const int* __restrict__ w, int ne) {
    int base = (blockIdx.x * blockDim.x + threadIdx.x) * 4;
    if (base >= ne) return;
    int lim = min(4, ne - base);
    int n64 = !g_not64;
#pragma unroll
    for (int q = 0; q < 4; q++) {
        if (q >= lim) break;
        int e = base + q;
        int s, d;
        if (n64) { s = w[2 * e]; d = w[2 * (ne + e)]; }
        else     { s = w[e];     d = w[ne + e]; }
        int pos = atomicAdd(&g_cursor[d], 1);
        g_csr[pos] = s;
    }
}

// ---------------- GEMM (2 threads per row; half = tid>>6 owns NOUT/2 cols) ----------------
// EPI: 0 = +bias store fp32 | 1 = +bias relu store fp32 | 2 = raw store AS FP16 into g_t
// INAFF: BN fold on input; INRELU: relu after affine; STATS: fuse BN col-stats (EPI==1 only)
template<int K, int NOUT, int EPI, bool INAFF, bool INRELU, bool STATS>
__global__ void __launch_bounds__(128)
gemm_kernel(const float* __restrict__ in, const float* __restrict__ W,
            const float* __restrict__ bias, float* __restrict__ out, int n,
            const float* __restrict__ stats, const float* __restrict__ gamma,
            const float* __restrict__ beta, float* __restrict__ stats_out)
{
    const int NH = NOUT / 2;
    __shared__ float Ws[K * NOUT];
    __shared__ float bs[NOUT];
    __shared__ float as_[64], cs_[64];
    __shared__ float sv[STATS ? 64 * 65 : 1];

    for (int i = threadIdx.x; i < K * NOUT; i += 128) Ws[i] = W[i];
    if (EPI != 2 && threadIdx.x < NOUT) bs[threadIdx.x] = bias[threadIdx.x];
    if (INAFF && threadIdx.x < K) {
        int t = threadIdx.x;
        float s = stats[t], s2 = stats[64 + t];
        float mu = s * INVN;
        float var = fmaxf(s2 * INVN - mu * mu, 0.0f);
        float a = rsqrtf(var + BN_EPS) * gamma[t];
        as_[t] = a;
        cs_[t] = fmaf(-mu, a, beta[t]);
    }
    __syncthreads();

    int r    = threadIdx.x & 63;
    int row  = blockIdx.x * 64 + r;
    int half = threadIdx.x >> 6;
    bool valid = row < n;
    if (!STATS && !valid) return;
    int rowc = valid ? row : (n - 1);

    const float4* xr4 = (const float4*)(in + (long long)rowc * K);

    float acc[NH];
#pragma unroll
    for (int j = 0; j < NH; j++) acc[j] = (EPI == 2) ? 0.0f : bs[half * NH + j];

#pragma unroll
    for (int kk = 0; kk < K; kk += 16) {
        float4 xv0 = xr4[kk / 4 + 0];
        float4 xv1 = xr4[kk / 4 + 1];
        float4 xv2 = xr4[kk / 4 + 2];
        float4 xv3 = xr4[kk / 4 + 3];
        float xs[16] = {xv0.x, xv0.y, xv0.z, xv0.w,
                        xv1.x, xv1.y, xv1.z, xv1.w,
                        xv2.x, xv2.y, xv2.z, xv2.w,
                        xv3.x, xv3.y, xv3.z, xv3.w};
        if (INAFF) {
#pragma unroll
            for (int i = 0; i < 16; i++) {
                xs[i] = fmaf(xs[i], as_[kk + i], cs_[kk + i]);
                if (INRELU) xs[i] = fmaxf(xs[i], 0.0f);
            }
        }
#pragma unroll
        for (int i = 0; i < 16; i++) {
            float xk = xs[i];
            const float* wr = Ws + (kk + i) * NOUT + half * NH;
#pragma unroll
            for (int j = 0; j < NH; j += 4) {
                float4 w = *(const float4*)(wr + j);
                acc[j + 0] = fmaf(xk, w.x, acc[j + 0]);
                acc[j + 1] = fmaf(xk, w.y, acc[j + 1]);
                acc[j + 2] = fmaf(xk, w.z, acc[j + 2]);
                acc[j + 3] = fmaf(xk, w.w, acc[j + 3]);
            }
        }
    }

    if (EPI == 2) {
        __half2 hbuf[NH / 2];
#pragma unroll
        for (int j = 0; j < NH; j += 2)
            hbuf[j / 2] = __floats2half2_rn(acc[j], acc[j + 1]);
        uint4* dst = (uint4*)((__half2*)g_t + (long long)row * (NOUT / 2) + half * (NH / 2));
        const uint4* src = (const uint4*)hbuf;
#pragma unroll
        for (int j = 0; j < NH / 8; j++) dst[j] = src[j];
    } else {
        if (EPI == 1) {
#pragma unroll
            for (int j = 0; j < NH; j++) acc[j] = fmaxf(acc[j], 0.0f);
        }
        if (valid) {
            float4* o4 = (float4*)(out + (long long)row * NOUT + half * NH);
#pragma unroll
            for (int j = 0; j < NH; j += 4)
                o4[j / 4] = make_float4(acc[j], acc[j + 1], acc[j + 2], acc[j + 3]);
        }
        if (STATS) {
#pragma unroll
            for (int j = 0; j < NH; j++)
                sv[r * 65 + half * NH + j] = valid ? acc[j] : 0.0f;
            __syncthreads();
            if (threadIdx.x < NOUT) {
                int c = threadIdx.x;
                float s = 0.0f, s2 = 0.0f;
#pragma unroll
                for (int r2 = 0; r2 < 64; r2++) {
                    float v = sv[r2 * 65 + c];
                    s += v;
                    s2 = fmaf(v, v, s2);
                }
                atomicAdd(&stats_out[c], s);
                atomicAdd(&stats_out[64 + c], s2);
            }
        }
    }
}

// ---------------- CSR gather (fp16 t, src-only CSR) + fused BN stats ----------------
__global__ void __launch_bounds__(256)
gather64_kernel(const float* __restrict__ bias, float* __restrict__ stats)
{
    __shared__ float sh[8][64];
    int warp = threadIdx.x >> 5;
    int lane = threadIdx.x & 31;
    int n = blockIdx.x * 8 + warp;

    float a0 = 0.0f, a1 = 0.0f;
    if (n < NN) {
        int e = g_start[n], e1 = g_start[n + 1];
        float dn = g_dinv[n];
        const __half2* Th = g_t;
        for (; e + 8 <= e1; e += 8) {
            int p[8];
#pragma unroll
            for (int q = 0; q < 8; q++) p[q] = g_csr[e + q];
            float cf[8];
#pragma unroll
            for (int q = 0; q < 8; q++) cf[q] = g_dinv[p[q]] * dn;
            __half2 v[8];
#pragma unroll
            for (int q = 0; q < 8; q++) v[q] = Th[p[q] * 32 + lane];
#pragma unroll
            for (int q = 0; q < 8; q++) {
                float2 vf = __half22float2(v[q]);
                a0 = fmaf(cf[q], vf.x, a0);
                a1 = fmaf(cf[q], vf.y, a1);
            }
        }
        for (; e < e1; e++) {
            int p = g_csr[e];
            float c = g_dinv[p] * dn;
            float2 vf = __half22float2(Th[p * 32 + lane]);
            a0 = fmaf(c, vf.x, a0); a1 = fmaf(c, vf.y, a1);
        }
        float d2 = dn * dn;
        float2 sv2 = __half22float2(Th[n * 32 + lane]);
        a0 = fmaf(sv2.x, d2, a0) + bias[2 * lane];
        a1 = fmaf(sv2.y, d2, a1) + bias[2 * lane + 1];
        ((float2*)g_agg)[n * 32 + lane] = make_float2(a0, a1);
    }
    sh[warp][2 * lane]     = a0;
    sh[warp][2 * lane + 1] = a1;
    __syncthreads();
    if (threadIdx.x < 64) {
        int c = threadIdx.x;
        float s = 0.0f, s2 = 0.0f;
#pragma unroll
        for (int wq = 0; wq < 8; wq++) {
            float v = sh[wq][c];
            s += v;
            s2 = fmaf(v, v, s2);
        }
        atomicAdd(&stats[c], s);
        atomicAdd(&stats[64 + c], s2);
    }
}

__global__ void __launch_bounds__(256)
gather32_kernel(const float* __restrict__ bias, float* __restrict__ stats)
{
    __shared__ float sh[8][32];
    int warp = threadIdx.x >> 5;
    int lane = threadIdx.x & 31;
    int n = blockIdx.x * 8 + warp;

    float a0 = 0.0f;
    if (n < NN) {
        int e = g_start[n], e1 = g_start[n + 1];
        float dn = g_dinv[n];
        const __half* T = (const __half*)g_t;   // 32 cols per row
        for (; e + 8 <= e1; e += 8) {
            int p[8];
#pragma unroll
            for (int q = 0; q < 8; q++) p[q] = g_csr[e + q];
            float cf[8];
#pragma unroll
            for (int q = 0; q < 8; q++) cf[q] = g_dinv[p[q]] * dn;
            __half v[8];
#pragma unroll
            for (int q = 0; q < 8; q++) v[q] = T[p[q] * 32 + lane];
#pragma unroll
            for (int q = 0; q < 8; q++)
                a0 = fmaf(cf[q], __half2float(v[q]), a0);
        }
        for (; e < e1; e++) {
            int p = g_csr[e];
            a0 = fmaf(g_dinv[p] * dn, __half2float(T[p * 32 + lane]), a0);
        }
        float d2 = dn * dn;
        a0 = fmaf(__half2float(T[n * 32 + lane]), d2, a0) + bias[lane];
        g_agg[n * 32 + lane] = a0;
    }
    sh[warp][lane] = a0;
    __syncthreads();
    if (threadIdx.x < 32) {
        int c = threadIdx.x;
        float s = 0.0f, s2 = 0.0f;
#pragma unroll
        for (int wq = 0; wq < 8; wq++) {
            float v = sh[wq][c];
            s += v;
            s2 = fmaf(v, v, s2);
        }
        atomicAdd(&stats[c], s);
        atomicAdd(&stats[64 + c], s2);
    }
}

// Final: BN params inline + row L2 normalize. Warp per row (lane == column).
__global__ void __launch_bounds__(256)
final_kernel(const float* __restrict__ stats, const float* __restrict__ gamma,
             const float* __restrict__ beta, float* __restrict__ out, int n)
{
    int t = blockIdx.x * blockDim.x + threadIdx.x;
    int row = t >> 5, lane = t & 31;
    if (row >= n) return;
    float s = stats[lane], s2 = stats[64 + lane];
    float mu = s * INVN;
    float var = fmaxf(s2 * INVN - mu * mu, 0.0f);
    float a = rsqrtf(var + BN_EPS) * gamma[lane];
    float c = fmaf(-mu, a, beta[lane]);
    float v = fmaf(g_agg[(long long)row * 32 + lane], a, c);
    float ss = v * v;
#pragma unroll
    for (int o = 16; o; o >>= 1) ss += __shfl_xor_sync(0xFFFFFFFFu, ss, o);
    out[(long long)row * 32 + lane] = v / fmaxf(sqrtf(ss), L2_EPS);
}

// ---------------- launch ----------------
extern "C" void kernel_launch(void* const* d_in, const int* in_sizes, int n_in,
                              void* d_out, int out_size)
{
    const float* x  = (const float*)d_in[0];
    const int*   ew = (const int*)d_in[1];
    const float* ne_w1 = (const float*)d_in[2];
    const float* ne_b1 = (const float*)d_in[3];
    const float* ne_g  = (const float*)d_in[4];
    const float* ne_be = (const float*)d_in[5];
    const float* ne_w2 = (const float*)d_in[6];
    const float* ne_b2 = (const float*)d_in[7];
    const float* c1_w = (const float*)d_in[8];
    const float* c1_b = (const float*)d_in[9];
    const float* g1   = (const float*)d_in[10];
    const float* be1  = (const float*)d_in[11];
    const float* c2_w = (const float*)d_in[12];
    const float* c2_b = (const float*)d_in[13];
    const float* g2   = (const float*)d_in[14];
    const float* be2  = (const float*)d_in[15];
    const float* c3_w = (const float*)d_in[16];
    const float* c3_b = (const float*)d_in[17];
    const float* g3   = (const float*)d_in[18];
    const float* be3  = (const float*)d_in[19];
    float* out = (float*)d_out;

    int ne = in_sizes[1] / 2;
    if (ne > MAXE) ne = MAXE;

    const int NB = (NN + 255) / 256;
    const int E4B = (ne / 4 + 256) / 256;
    const int GB = (NN + 63) / 64;
    const int WB = (NN + 7) / 8;

    float* dAgg; cudaGetSymbolAddress((void**)&dAgg, g_agg);
    float* dH;   cudaGetSymbolAddress((void**)&dH,   g_h);
    float* dS;   cudaGetSymbolAddress((void**)&dS,   g_stats4);
    float* sA = dS, *sB = dS + 128, *sC = dS + 256, *sD = dS + 384;

    static cudaStream_t s1 = nullptr;
    static cudaEvent_t ev0 = nullptr, ev1 = nullptr;
    if (!s1) {
        cudaStreamCreateWithFlags(&s1, cudaStreamNonBlocking);
        cudaEventCreateWithFlags(&ev0, cudaEventDisableTiming);
        cudaEventCreateWithFlags(&ev1, cudaEventDisableTiming);
    }

    // ---- init (zeros + dtype probe), then fork
    init_kernel<<<NB, 256>>>(ew, ne);
    cudaEventRecord(ev0, 0);

    // ---- CSR build on side stream (overlaps encoder + conv1 GEMM)
    cudaStreamWaitEvent(s1, ev0, 0);
    deg_kernel<<<E4B, 256, 0, s1>>>(ew, ne);
    scan_lb_kernel<<<SBLKS, SCHUNK, 0, s1>>>();
    place_kernel<<<E4B, 256, 0, s1>>>(ew, ne);
    cudaEventRecord(ev1, s1);

    // ---- node encoder on main stream (stats fused into GEMM-1 epilogue)
    gemm_kernel<32, 64, 1, false, false, true><<<GB, 128>>>(x, ne_w1, ne_b1, dAgg, NN, nullptr, nullptr, nullptr, sA);
    gemm_kernel<64, 64, 0, true, false, false><<<GB, 128>>>(dAgg, ne_w2, ne_b2, dH, NN, sA, ne_g, ne_be, nullptr);

    // ---- conv layer 1 GEMM (no CSR needed yet; extends side-chain shadow)
    gemm_kernel<64, 64, 2, false, false, false><<<GB, 128>>>(dH, c1_w, c1_b, nullptr, NN, nullptr, nullptr, nullptr, nullptr);

    // join: gathers need the CSR
    cudaStreamWaitEvent(0, ev1, 0);

    gather64_kernel<<<WB, 256>>>(c1_b, sB);

    // ---- conv layer 2 (BN+relu folded into GEMM input; stats fused into gather)
    gemm_kernel<64, 64, 2, true, true, false><<<GB, 128>>>(dAgg, c2_w, c2_b, nullptr, NN, sB, g1, be1, nullptr);
    gather64_kernel<<<WB, 256>>>(c2_b, sC);

    // ---- conv layer 3 (out=32)
    gemm_kernel<64, 32, 2, true, true, false><<<GB, 128>>>(dAgg, c3_w, c3_b, nullptr, NN, sC, g2, be2, nullptr);
    gather32_kernel<<<WB, 256>>>(c3_b, sD);

    // ---- final BN + L2 normalize
    final_kernel<<<(NN * 32 + 255) / 256, 256>>>(sD, g3, be3, out, NN);
}

// round 12
// speedup vs baseline: 1.7214x; 1.0642x over previous
#include <cuda_runtime.h>
#include <cuda_fp16.h>
#include <math.h>

#define NN 50000
#define MAXE 1700000
#define BN_EPS 1e-5f
#define L2_EPS 1e-12f
#define INVN (1.0f / 50000.0f)

#define SCHUNK 256
#define SBLKS ((NN + SCHUNK - 1) / SCHUNK)   // 196
#define LMASK ((1u << 30) - 1u)

// ---------------- scratch (static device globals; no allocation) ----------------
__device__ float g_dinv[NN];                       // rsqrt(degree+1)
__device__ __align__(16) __half2 g_t[NN * 32];     // t = h @ W in fp16
__device__ __align__(16) float g_agg[NN * 64];     // aggregation result / encoder temp
__device__ int   g_degcnt[NN];                     // in-degree (no self loop)
__device__ int   g_start[NN + 1];                  // CSR row starts
__device__ int   g_cursor[NN];                     // placement cursors
__device__ unsigned int g_look[SBLKS];             // lookback word
__device__ int   g_csr[MAXE];                      // src only (4B), grouped by dst
__device__ float g_stats4[4 * 128];                // 4 BN stat slots
__device__ int   g_not64;                          // 1 if edge_index is int32 layout

// ---------------- init: zero degcnt + stats + lookback; block 0 probes dtype ----------------
__global__ void init_kernel(const int* __restrict__ w, int ne) {
    int i = blockIdx.x * blockDim.x + threadIdx.x;
    if (i < NN) g_degcnt[i] = 0;
    if (i < 512) g_stats4[i] = 0.0f;
    if (i < SBLKS) g_look[i] = 0u;
    if (blockIdx.x == 0) {
        int nz = 0;
        for (int k = 2 * threadIdx.x + 1; k < 2048 && k < 2 * ne; k += 512)
            nz |= (w[k] != 0);
        if (nz) atomicExch(&g_not64, 1);
    }
}

// in-degree histogram, 8 edges per thread
__global__ void deg_kernel(const int* __restrict__ w, int ne) {
    int base = (blockIdx.x * blockDim.x + threadIdx.x) * 8;
    if (base >= ne) return;
    int lim = min(8, ne - base);
    if (g_not64) {
        const int* dstp = w + ne + base;
#pragma unroll
        for (int q = 0; q < 8; q++)
            if (q < lim) atomicAdd(&g_degcnt[dstp[q]], 1);
    } else {
        const int* dstp = w + 2 * (ne + base);
#pragma unroll
        for (int q = 0; q < 8; q++)
            if (q < lim) atomicAdd(&g_degcnt[dstp[2 * q]], 1);
    }
}

// ---------------- single-pass decoupled-lookback scan ----------------
__global__ void __launch_bounds__(SCHUNK)
scan_lb_kernel() {
    int b = blockIdx.x;
    int i = b * SCHUNK + threadIdx.x;
    int v = (i < NN) ? g_degcnt[i] : 0;
    int lane = threadIdx.x & 31, warp = threadIdx.x >> 5;

    int x = v;
#pragma unroll
    for (int o = 1; o < 32; o <<= 1) {
        int y = __shfl_up_sync(0xFFFFFFFFu, x, o);
        if (lane >= o) x += y;
    }
    __shared__ int wsum[8];
    if (lane == 31) wsum[warp] = x;
    __syncthreads();
    if (warp == 0) {
        int w = (lane < 8) ? wsum[lane] : 0;
#pragma unroll
        for (int o = 1; o < 8; o <<= 1) {
            int y = __shfl_up_sync(0xFFFFFFFFu, w, o);
            if (lane >= o) w += y;
        }
        if (lane < 8) wsum[lane] = w;
    }
    __syncthreads();
    int incl_local = x + (warp ? wsum[warp - 1] : 0);
    int block_total = wsum[7];

    __shared__ int s_prev;
    if (threadIdx.x == 0) {
        atomicExch(&g_look[b], (1u << 30) | (unsigned)block_total);
        int run = 0;
        for (int j = b - 1; j >= 0; ) {
            unsigned u = atomicAdd(&g_look[j], 0u);
            if (u == 0u) continue;
            if ((u >> 30) == 2u) { run += (int)(u & LMASK); break; }
            run += (int)(u & LMASK); j--;
        }
        atomicExch(&g_look[b], (2u << 30) | (unsigned)(run + block_total));
        s_prev = run;
    }
    __syncthreads();

    int excl = incl_local - v + s_prev;
    if (i < NN) {
        g_start[i] = excl;
        g_cursor[i] = excl;
        g_dinv[i] = rsqrtf((float)v + 1.0f);
        if (i == NN - 1) g_start[NN] = excl + v;
    }
}

// place edges into CSR bins (src only), 8 edges per thread
__global__ void place_kernel(const int* __restrict__ w, int ne) {
    int base = (blockIdx.x * blockDim.x + threadIdx.x) * 8;
    if (base >= ne) return;
    int lim = min(8, ne - base);
    int n64 = !g_not64;
    int s[8], d[8];
#pragma unroll
    for (int q = 0; q < 8; q++) {
        if (q >= lim) break;
        int e = base + q;
        if (n64) { s[q] = w[2 * e]; d[q] = w[2 * (ne + e)]; }
        else     { s[q] = w[e];     d[q] = w[ne + e]; }
    }
#pragma unroll
    for (int q = 0; q < 8; q++) {
        if (q >= lim) break;
        int pos = atomicAdd(&g_cursor[d[q]], 1);
        g_csr[pos] = s[q];
    }
}

// ---------------- GEMM (2 threads per row; half = tid>>6 owns NOUT/2 cols) ----------------
// EPI: 0 = +bias store fp32 | 1 = +bias relu store fp32 | 2 = raw store AS FP16 into g_t
// INAFF: BN fold on input; INRELU: relu after affine; STATS: fuse BN col-stats (EPI==1 only)
template<int K, int NOUT, int EPI, bool INAFF, bool INRELU, bool STATS>
__global__ void __launch_bounds__(128)
gemm_kernel(const float* __restrict__ in, const float* __restrict__ W,
            const float* __restrict__ bias, float* __restrict__ out, int n,
            const float* __restrict__ stats, const float* __restrict__ gamma,
            const float* __restrict__ beta, float* __restrict__ stats_out)
{
    const int NH = NOUT / 2;
    __shared__ float Ws[K * NOUT];
    __shared__ float bs[NOUT];
    __shared__ float as_[64], cs_[64];
    __shared__ float sv[STATS ? 64 * 65 : 1];

    for (int i = threadIdx.x; i < K * NOUT; i += 128) Ws[i] = W[i];
    if (EPI != 2 && threadIdx.x < NOUT) bs[threadIdx.x] = bias[threadIdx.x];
    if (INAFF && threadIdx.x < K) {
        int t = threadIdx.x;
        float s = stats[t], s2 = stats[64 + t];
        float mu = s * INVN;
        float var = fmaxf(s2 * INVN - mu * mu, 0.0f);
        float a = rsqrtf(var + BN_EPS) * gamma[t];
        as_[t] = a;
        cs_[t] = fmaf(-mu, a, beta[t]);
    }
    __syncthreads();

    int r    = threadIdx.x & 63;
    int row  = blockIdx.x * 64 + r;
    int half = threadIdx.x >> 6;
    bool valid = row < n;
    if (!STATS && !valid) return;
    int rowc = valid ? row : (n - 1);

    const float4* xr4 = (const float4*)(in + (long long)rowc * K);

    float acc[NH];
#pragma unroll
    for (int j = 0; j < NH; j++) acc[j] = (EPI == 2) ? 0.0f : bs[half * NH + j];

#pragma unroll
    for (int kk = 0; kk < K; kk += 16) {
        float4 xv0 = xr4[kk / 4 + 0];
        float4 xv1 = xr4[kk / 4 + 1];
        float4 xv2 = xr4[kk / 4 + 2];
        float4 xv3 = xr4[kk / 4 + 3];
        float xs[16] = {xv0.x, xv0.y, xv0.z, xv0.w,
                        xv1.x, xv1.y, xv1.z, xv1.w,
                        xv2.x, xv2.y, xv2.z, xv2.w,
                        xv3.x, xv3.y, xv3.z, xv3.w};
        if (INAFF) {
#pragma unroll
            for (int i = 0; i < 16; i++) {
                xs[i] = fmaf(xs[i], as_[kk + i], cs_[kk + i]);
                if (INRELU) xs[i] = fmaxf(xs[i], 0.0f);
            }
        }
#pragma unroll
        for (int i = 0; i < 16; i++) {
            float xk = xs[i];
            const float* wr = Ws + (kk + i) * NOUT + half * NH;
#pragma unroll
            for (int j = 0; j < NH; j += 4) {
                float4 w = *(const float4*)(wr + j);
                acc[j + 0] = fmaf(xk, w.x, acc[j + 0]);
                acc[j + 1] = fmaf(xk, w.y, acc[j + 1]);
                acc[j + 2] = fmaf(xk, w.z, acc[j + 2]);
                acc[j + 3] = fmaf(xk, w.w, acc[j + 3]);
            }
        }
    }

    if (EPI == 2) {
        __half2 hbuf[NH / 2];
#pragma unroll
        for (int j = 0; j < NH; j += 2)
            hbuf[j / 2] = __floats2half2_rn(acc[j], acc[j + 1]);
        uint4* dst = (uint4*)((__half2*)g_t + (long long)row * (NOUT / 2) + half * (NH / 2));
        const uint4* src = (const uint4*)hbuf;
#pragma unroll
        for (int j = 0; j < NH / 8; j++) dst[j] = src[j];
    } else {
        if (EPI == 1) {
#pragma unroll
            for (int j = 0; j < NH; j++) acc[j] = fmaxf(acc[j], 0.0f);
        }
        if (valid) {
            float4* o4 = (float4*)(out + (long long)row * NOUT + half * NH);
#pragma unroll
            for (int j = 0; j < NH; j += 4)
                o4[j / 4] = make_float4(acc[j], acc[j + 1], acc[j + 2], acc[j + 3]);
        }
        if (STATS) {
#pragma unroll
            for (int j = 0; j < NH; j++)
                sv[r * 65 + half * NH + j] = valid ? acc[j] : 0.0f;
            __syncthreads();
            if (threadIdx.x < NOUT) {
                int c = threadIdx.x;
                float s = 0.0f, s2 = 0.0f;
#pragma unroll
                for (int r2 = 0; r2 < 64; r2++) {
                    float v = sv[r2 * 65 + c];
                    s += v;
                    s2 = fmaf(v, v, s2);
                }
                atomicAdd(&stats_out[c], s);
                atomicAdd(&stats_out[64 + c], s2);
            }
        }
    }
}

// ---------------- fused encoder GEMM-2 + conv1 GEMM ----------------
// h = BN(in)@W2 + b2  (block-local smem exchange)  then  t = h@c1W -> g_t fp16
__global__ void __launch_bounds__(128)
gemm12_kernel(const float* __restrict__ in, const float* __restrict__ W2,
              const float* __restrict__ b2, const float* __restrict__ c1W,
              const float* __restrict__ stats, const float* __restrict__ gamma,
              const float* __restrict__ beta, int n)
{
    __shared__ float u[64 * 65];        // phase 1: W2 (64*64); phase 2: h exchange (64*65)
    __shared__ float Ws2[64 * 64];      // c1W
    __shared__ float bs[64], as_[64], cs_[64];

    for (int i = threadIdx.x; i < 64 * 64; i += 128) { u[i] = W2[i]; Ws2[i] = c1W[i]; }
    if (threadIdx.x < 64) {
        int t = threadIdx.x;
        bs[t] = b2[t];
        float s = stats[t], s2 = stats[64 + t];
        float mu = s * INVN;
        float var = fmaxf(s2 * INVN - mu * mu, 0.0f);
        float a = rsqrtf(var + BN_EPS) * gamma[t];
        as_[t] = a;
        cs_[t] = fmaf(-mu, a, beta[t]);
    }
    __syncthreads();

    int r    = threadIdx.x & 63;
    int row  = blockIdx.x * 64 + r;
    int half = threadIdx.x >> 6;
    bool valid = row < n;
    int rowc = valid ? row : (n - 1);

    const float4* xr4 = (const float4*)(in + (long long)rowc * 64);

    // ---- phase 1: h-half = BN(x)@W2 + b2
    float acc[32];
#pragma unroll
    for (int j = 0; j < 32; j++) acc[j] = bs[half * 32 + j];

#pragma unroll
    for (int kk = 0; kk < 64; kk += 16) {
        float4 xv0 = xr4[kk / 4 + 0];
        float4 xv1 = xr4[kk / 4 + 1];
        float4 xv2 = xr4[kk / 4 + 2];
        float4 xv3 = xr4[kk / 4 + 3];
        float xs[16] = {xv0.x, xv0.y, xv0.z, xv0.w,
                        xv1.x, xv1.y, xv1.z, xv1.w,
                        xv2.x, xv2.y, xv2.z, xv2.w,
                        xv3.x, xv3.y, xv3.z, xv3.w};
#pragma unroll
        for (int i = 0; i < 16; i++)
            xs[i] = fmaf(xs[i], as_[kk + i], cs_[kk + i]);
#pragma unroll
        for (int i = 0; i < 16; i++) {
            float xk = xs[i];
            const float* wr = u + (kk + i) * 64 + half * 32;
#pragma unroll
            for (int j = 0; j < 32; j += 4) {
                float4 w = *(const float4*)(wr + j);
                acc[j + 0] = fmaf(xk, w.x, acc[j + 0]);
                acc[j + 1] = fmaf(xk, w.y, acc[j + 1]);
                acc[j + 2] = fmaf(xk, w.z, acc[j + 2]);
                acc[j + 3] = fmaf(xk, w.w, acc[j + 3]);
            }
        }
    }

    // ---- exchange h through smem (u is done serving as W2)
    __syncthreads();
#pragma unroll
    for (int j = 0; j < 32; j++) u[r * 65 + half * 32 + j] = acc[j];
    __syncthreads();

    // ---- phase 2: t-half = h@c1W  (raw, fp16 store; bias applied in gather)
    float acc2[32];
#pragma unroll
    for (int j = 0; j < 32; j++) acc2[j] = 0.0f;
#pragma unroll
    for (int k = 0; k < 64; k++) {
        float hk = u[r * 65 + k];
        const float* wr = Ws2 + k * 64 + half * 32;
#pragma unroll
        for (int j = 0; j < 32; j += 4) {
            float4 w = *(const float4*)(wr + j);
            acc2[j + 0] = fmaf(hk, w.x, acc2[j + 0]);
            acc2[j + 1] = fmaf(hk, w.y, acc2[j + 1]);
            acc2[j + 2] = fmaf(hk, w.z, acc2[j + 2]);
            acc2[j + 3] = fmaf(hk, w.w, acc2[j + 3]);
        }
    }

    if (valid) {
        __half2 hbuf[16];
#pragma unroll
        for (int j = 0; j < 32; j += 2)
            hbuf[j / 2] = __floats2half2_rn(acc2[j], acc2[j + 1]);
        uint4* dst = (uint4*)((__half2*)g_t + (long long)row * 32 + half * 16);
        const uint4* src = (const uint4*)hbuf;
#pragma unroll
        for (int j = 0; j < 4; j++) dst[j] = src[j];
    }
}

// ---------------- CSR gather (fp16 t, src-only CSR) + fused BN stats ----------------
__global__ void __launch_bounds__(256)
gather64_kernel(const float* __restrict__ bias, float* __restrict__ stats)
{
    __shared__ float sh[8][64];
    int warp = threadIdx.x >> 5;
    int lane = threadIdx.x & 31;
    int n = blockIdx.x * 8 + warp;

    float a0 = 0.0f, a1 = 0.0f;
    if (n < NN) {
        int e = g_start[n], e1 = g_start[n + 1];
        float dn = g_dinv[n];
        const __half2* Th = g_t;
        for (; e + 8 <= e1; e += 8) {
            int p[8];
#pragma unroll
            for (int q = 0; q < 8; q++) p[q] = g_csr[e + q];
            float cf[8];
#pragma unroll
            for (int q = 0; q < 8; q++) cf[q] = g_dinv[p[q]] * dn;
            __half2 v[8];
#pragma unroll
            for (int q = 0; q < 8; q++) v[q] = Th[p[q] * 32 + lane];
#pragma unroll
            for (int q = 0; q < 8; q++) {
                float2 vf = __half22float2(v[q]);
                a0 = fmaf(cf[q], vf.x, a0);
                a1 = fmaf(cf[q], vf.y, a1);
            }
        }
        for (; e < e1; e++) {
            int p = g_csr[e];
            float c = g_dinv[p] * dn;
            float2 vf = __half22float2(Th[p * 32 + lane]);
            a0 = fmaf(c, vf.x, a0); a1 = fmaf(c, vf.y, a1);
        }
        float d2 = dn * dn;
        float2 sv2 = __half22float2(Th[n * 32 + lane]);
        a0 = fmaf(sv2.x, d2, a0) + bias[2 * lane];
        a1 = fmaf(sv2.y, d2, a1) + bias[2 * lane + 1];
        ((float2*)g_agg)[n * 32 + lane] = make_float2(a0, a1);
    }
    sh[warp][2 * lane]     = a0;
    sh[warp][2 * lane + 1] = a1;
    __syncthreads();
    if (threadIdx.x < 64) {
        int c = threadIdx.x;
        float s = 0.0f, s2 = 0.0f;
#pragma unroll
        for (int wq = 0; wq < 8; wq++) {
            float v = sh[wq][c];
            s += v;
            s2 = fmaf(v, v, s2);
        }
        atomicAdd(&stats[c], s);
        atomicAdd(&stats[64 + c], s2);
    }
}

__global__ void __launch_bounds__(256)
gather32_kernel(const float* __restrict__ bias, float* __restrict__ stats)
{
    __shared__ float sh[8][32];
    int warp = threadIdx.x >> 5;
    int lane = threadIdx.x & 31;
    int n = blockIdx.x * 8 + warp;

    float a0 = 0.0f;
    if (n < NN) {
        int e = g_start[n], e1 = g_start[n + 1];
        float dn = g_dinv[n];
        const __half* T = (const __half*)g_t;   // 32 cols per row
        for (; e + 8 <= e1; e += 8) {
            int p[8];
#pragma unroll
            for (int q = 0; q < 8; q++) p[q] = g_csr[e + q];
            float cf[8];
#pragma unroll
            for (int q = 0; q < 8; q++) cf[q] = g_dinv[p[q]] * dn;
            __half v[8];
#pragma unroll
            for (int q = 0; q < 8; q++) v[q] = T[p[q] * 32 + lane];
#pragma unroll
            for (int q = 0; q < 8; q++)
                a0 = fmaf(cf[q], __half2float(v[q]), a0);
        }
        for (; e < e1; e++) {
            int p = g_csr[e];
            a0 = fmaf(g_dinv[p] * dn, __half2float(T[p * 32 + lane]), a0);
        }
        float d2 = dn * dn;
        a0 = fmaf(__half2float(T[n * 32 + lane]), d2, a0) + bias[lane];
        g_agg[n * 32 + lane] = a0;
    }
    sh[warp][lane] = a0;
    __syncthreads();
    if (threadIdx.x < 32) {
        int c = threadIdx.x;
        float s = 0.0f, s2 = 0.0f;
#pragma unroll
        for (int wq = 0; wq < 8; wq++) {
            float v = sh[wq][c];
            s += v;
            s2 = fmaf(v, v, s2);
        }
        atomicAdd(&stats[c], s);
        atomicAdd(&stats[64 + c], s2);
    }
}

// Final: BN params inline + row L2 normalize. Warp per row (lane == column).
__global__ void __launch_bounds__(256)
final_kernel(const float* __restrict__ stats, const float* __restrict__ gamma,
             const float* __restrict__ beta, float* __restrict__ out, int n)
{
    int t = blockIdx.x * blockDim.x + threadIdx.x;
    int row = t >> 5, lane = t & 31;
    if (row >= n) return;
    float s = stats[lane], s2 = stats[64 + lane];
    float mu = s * INVN;
    float var = fmaxf(s2 * INVN - mu * mu, 0.0f);
    float a = rsqrtf(var + BN_EPS) * gamma[lane];
    float c = fmaf(-mu, a, beta[lane]);
    float v = fmaf(g_agg[(long long)row * 32 + lane], a, c);
    float ss = v * v;
#pragma unroll
    for (int o = 16; o; o >>= 1) ss += __shfl_xor_sync(0xFFFFFFFFu, ss, o);
    out[(long long)row * 32 + lane] = v / fmaxf(sqrtf(ss), L2_EPS);
}

// ---------------- launch ----------------
extern "C" void kernel_launch(void* const* d_in, const int* in_sizes, int n_in,
                              void* d_out, int out_size)
{
    const float* x  = (const float*)d_in[0];
    const int*   ew = (const int*)d_in[1];
    const float* ne_w1 = (const float*)d_in[2];
    const float* ne_b1 = (const float*)d_in[3];
    const float* ne_g  = (const float*)d_in[4];
    const float* ne_be = (const float*)d_in[5];
    const float* ne_w2 = (const float*)d_in[6];
    const float* ne_b2 = (const float*)d_in[7];
    const float* c1_w = (const float*)d_in[8];
    const float* c1_b = (const float*)d_in[9];
    const float* g1   = (const float*)d_in[10];
    const float* be1  = (const float*)d_in[11];
    const float* c2_w = (const float*)d_in[12];
    const float* c2_b = (const float*)d_in[13];
    const float* g2   = (const float*)d_in[14];
    const float* be2  = (const float*)d_in[15];
    const float* c3_w = (const float*)d_in[16];
    const float* c3_b = (const float*)d_in[17];
    const float* g3   = (const float*)d_in[18];
    const float* be3  = (const float*)d_in[19];
    float* out = (float*)d_out;

    int ne = in_sizes[1] / 2;
    if (ne > MAXE) ne = MAXE;

    const int NB = (NN + 255) / 256;
    const int E8B = (ne / 8 + 256) / 256;   // 8-edges-per-thread blocks (covers tail)
    const int GB = (NN + 63) / 64;
    const int WB = (NN + 7) / 8;

    float* dAgg; cudaGetSymbolAddress((void**)&dAgg, g_agg);
    float* dS;   cudaGetSymbolAddress((void**)&dS,   g_stats4);
    float* sA = dS, *sB = dS + 128, *sC = dS + 256, *sD = dS + 384;

    static cudaStream_t s1 = nullptr;
    static cudaEvent_t ev0 = nullptr, ev1 = nullptr;
    if (!s1) {
        cudaStreamCreateWithFlags(&s1, cudaStreamNonBlocking);
        cudaEventCreateWithFlags(&ev0, cudaEventDisableTiming);
        cudaEventCreateWithFlags(&ev1, cudaEventDisableTiming);
    }

    // ---- init (zeros + dtype probe), then fork
    init_kernel<<<NB, 256>>>(ew, ne);
    cudaEventRecord(ev0, 0);

    // ---- CSR build on side stream (overlaps encoder + fused GEMM)
    cudaStreamWaitEvent(s1, ev0, 0);
    deg_kernel<<<E8B, 256, 0, s1>>>(ew, ne);
    scan_lb_kernel<<<SBLKS, SCHUNK, 0, s1>>>();
    place_kernel<<<E8B, 256, 0, s1>>>(ew, ne);
    cudaEventRecord(ev1, s1);

    // ---- encoder GEMM-1 (stats fused), then fused encoder GEMM-2 + conv1 GEMM
    gemm_kernel<32, 64, 1, false, false, true><<<GB, 128>>>(x, ne_w1, ne_b1, dAgg, NN, nullptr, nullptr, nullptr, sA);
    gemm12_kernel<<<GB, 128>>>(dAgg, ne_w2, ne_b2, c1_w, sA, ne_g, ne_be, NN);

    // join: gathers need the CSR
    cudaStreamWaitEvent(0, ev1, 0);

    gather64_kernel<<<WB, 256>>>(c1_b, sB);

    // ---- conv layer 2 (BN+relu folded into GEMM input; stats fused into gather)
    gemm_kernel<64, 64, 2, true, true, false><<<GB, 128>>>(dAgg, c2_w, c2_b, nullptr, NN, sB, g1, be1, nullptr);
    gather64_kernel<<<WB, 256>>>(c2_b, sC);

    // ---- conv layer 3 (out=32)
    gemm_kernel<64, 32, 2, true, true, false><<<GB, 128>>>(dAgg, c3_w, c3_b, nullptr, NN, sC, g2, be2, nullptr);
    gather32_kernel<<<WB, 256>>>(c3_b, sD);

    // ---- final BN + L2 normalize
    final_kernel<<<(NN * 32 + 255) / 256, 256>>>(sD, g3, be3, out, NN);
}